// round 1
// baseline (speedup 1.0000x reference)
#include <cuda_runtime.h>

#define B_  2
#define S_  2048
#define D_  1024
#define H_  16
#define HD_ 64

// Scratch (no cudaMalloc allowed): qkv after proj+RoPE, attention output
__device__ float g_qkv[(size_t)B_ * S_ * 3 * D_];   // [B*S, 3*D]
__device__ float g_attn[(size_t)B_ * S_ * D_];      // [B*S, D]

// ---------------------------------------------------------------------------
// SGEMM: C[M,N] = A[M,K] @ W[N,K]^T + bias[N], optional fused RoPE on n<2*D_
// 128x128 block tile, BK=8, 256 threads, 8x8 per-thread microtile.
// All dims divisible by tiles for this problem (no bounds checks).
// ---------------------------------------------------------------------------
template <bool ROPE>
__global__ void __launch_bounds__(256)
sgemm_kernel(const float* __restrict__ A, const float* __restrict__ W,
             const float* __restrict__ bias, const float* __restrict__ rot,
             float* __restrict__ C, int M, int N, int K)
{
    __shared__ float As[8][132];
    __shared__ float Ws[8][132];

    const int tid  = threadIdx.x;
    const int tx   = tid & 15;    // 0..15  (N direction)
    const int ty   = tid >> 4;    // 0..15  (M direction)
    const int arow = tid >> 1;    // 0..127
    const int acol = (tid & 1) * 4;

    const float* Ap = A + (size_t)(blockIdx.y * 128 + arow) * K + acol;
    const float* Wp = W + (size_t)(blockIdx.x * 128 + arow) * K + acol;

    float c[8][8];
#pragma unroll
    for (int i = 0; i < 8; i++)
#pragma unroll
        for (int j = 0; j < 8; j++) c[i][j] = 0.0f;

    for (int k0 = 0; k0 < K; k0 += 8) {
        float4 av = *(const float4*)(Ap + k0);
        float4 wv = *(const float4*)(Wp + k0);
        As[acol + 0][arow] = av.x;
        As[acol + 1][arow] = av.y;
        As[acol + 2][arow] = av.z;
        As[acol + 3][arow] = av.w;
        Ws[acol + 0][arow] = wv.x;
        Ws[acol + 1][arow] = wv.y;
        Ws[acol + 2][arow] = wv.z;
        Ws[acol + 3][arow] = wv.w;
        __syncthreads();

#pragma unroll
        for (int kk = 0; kk < 8; kk++) {
            float a[8], b[8];
            *(float4*)&a[0] = *(const float4*)&As[kk][ty * 8];
            *(float4*)&a[4] = *(const float4*)&As[kk][ty * 8 + 4];
            *(float4*)&b[0] = *(const float4*)&Ws[kk][tx * 8];
            *(float4*)&b[4] = *(const float4*)&Ws[kk][tx * 8 + 4];
#pragma unroll
            for (int i = 0; i < 8; i++)
#pragma unroll
                for (int j = 0; j < 8; j++)
                    c[i][j] += a[i] * b[j];
        }
        __syncthreads();
    }

    // Epilogue: bias + optional RoPE on column pairs (n even)
    const int row0 = blockIdx.y * 128 + ty * 8;
    const int col0 = blockIdx.x * 128 + tx * 8;
#pragma unroll
    for (int i = 0; i < 8; i++) {
        const int row = row0 + i;
        const int s   = row & (S_ - 1);   // row = b*S + s, S power of 2
#pragma unroll
        for (int j = 0; j < 8; j += 2) {
            const int n = col0 + j;
            float e = c[i][j]     + bias[n];
            float o = c[i][j + 1] + bias[n + 1];
            float o0 = e, o1 = o;
            if (ROPE && n < 2 * D_) {
                const int d2 = n & (HD_ - 1);          // even
                const float cs = rot[s * HD_ + d2];
                const float sn = rot[s * HD_ + d2 + 1];
                o0 = e * cs - o * sn;
                o1 = e * sn + o * cs;
            }
            C[(size_t)row * N + n]     = o0;
            C[(size_t)row * N + n + 1] = o1;
        }
    }
}

// ---------------------------------------------------------------------------
// Flash attention, fp32. One thread per query row, 64-row q blocks.
// grid (S/64, H, B), block 64 threads. K/V tiles of 64 keys in SMEM.
// ---------------------------------------------------------------------------
__global__ void __launch_bounds__(64)
attn_kernel(const float* __restrict__ qkv, float* __restrict__ out)
{
    __shared__ float ks[64][64];
    __shared__ float vs[64][64];
    __shared__ float sc[64][64];   // sc[key][query-thread] -> conflict-free

    const int tid = threadIdx.x;
    const int b   = blockIdx.z;
    const int h   = blockIdx.y;
    const int rq  = blockIdx.x * 64 + tid;

    const float* qp = qkv + ((size_t)(b * S_ + rq) * 3 * D_) + h * HD_;
    float q[64];
#pragma unroll
    for (int d = 0; d < 64; d++) q[d] = qp[d] * 0.125f;   // scale = 1/sqrt(64)

    float o[64];
#pragma unroll
    for (int d = 0; d < 64; d++) o[d] = 0.0f;
    float m = -1e30f;
    float l = 0.0f;

    const int lj  = tid >> 4;   // row-in-group (0..3)
    const int ld4 = tid & 15;   // float4 index within a 64-float row

    for (int kt = 0; kt < S_; kt += 64) {
        // Cooperative coalesced load of 64x64 K and V tiles
        const float* kbase = qkv + ((size_t)(b * S_ + kt) * 3 * D_) + D_ + h * HD_;
        const float* vbase = kbase + D_;
#pragma unroll
        for (int jg = 0; jg < 16; jg++) {
            const int j = jg * 4 + lj;
            *(float4*)&ks[j][ld4 * 4] =
                *(const float4*)(kbase + (size_t)j * 3 * D_ + ld4 * 4);
            *(float4*)&vs[j][ld4 * 4] =
                *(const float4*)(vbase + (size_t)j * 3 * D_ + ld4 * 4);
        }
        __syncthreads();

        // Pass 1: scores + tile max
        float tmax = -1e30f;
        for (int j = 0; j < 64; j++) {
            float s0 = 0.f, s1 = 0.f, s2 = 0.f, s3 = 0.f;
            const float4* kr = (const float4*)&ks[j][0];
#pragma unroll
            for (int d4 = 0; d4 < 16; d4++) {
                const float4 kv = kr[d4];
                s0 += q[d4 * 4 + 0] * kv.x;
                s1 += q[d4 * 4 + 1] * kv.y;
                s2 += q[d4 * 4 + 2] * kv.z;
                s3 += q[d4 * 4 + 3] * kv.w;
            }
            const float sv = (s0 + s1) + (s2 + s3);
            sc[j][tid] = sv;
            tmax = fmaxf(tmax, sv);
        }

        // Online softmax rescale
        const float mnew  = fmaxf(m, tmax);
        const float alpha = __expf(m - mnew);
        l *= alpha;
#pragma unroll
        for (int d = 0; d < 64; d++) o[d] *= alpha;

        // Pass 2: exp + PV accumulation
        for (int j = 0; j < 64; j++) {
            const float p = __expf(sc[j][tid] - mnew);
            l += p;
            const float4* vr = (const float4*)&vs[j][0];
#pragma unroll
            for (int d4 = 0; d4 < 16; d4++) {
                const float4 vv = vr[d4];
                o[d4 * 4 + 0] += p * vv.x;
                o[d4 * 4 + 1] += p * vv.y;
                o[d4 * 4 + 2] += p * vv.z;
                o[d4 * 4 + 3] += p * vv.w;
            }
        }
        m = mnew;
        __syncthreads();
    }

    const float inv = 1.0f / l;
    float* op = out + ((size_t)(b * S_ + rq) * D_) + h * HD_;
#pragma unroll
    for (int d = 0; d < 64; d++) op[d] = o[d] * inv;
}

// ---------------------------------------------------------------------------
extern "C" void kernel_launch(void* const* d_in, const int* in_sizes, int n_in,
                              void* d_out, int out_size)
{
    const float* x     = (const float*)d_in[0];
    const float* rot   = (const float*)d_in[1];
    const float* w_qkv = (const float*)d_in[2];
    const float* b_qkv = (const float*)d_in[3];
    const float* w_o   = (const float*)d_in[4];
    const float* b_o   = (const float*)d_in[5];
    float* out = (float*)d_out;

    float* qkv  = nullptr;
    float* attn = nullptr;
    cudaGetSymbolAddress((void**)&qkv,  g_qkv);
    cudaGetSymbolAddress((void**)&attn, g_attn);

    const int M = B_ * S_;       // 4096

    // 1) QKV projection + bias + RoPE  -> g_qkv [M, 3*D]
    {
        dim3 grid((3 * D_) / 128, M / 128);
        sgemm_kernel<true><<<grid, 256>>>(x, w_qkv, b_qkv, rot, qkv,
                                          M, 3 * D_, D_);
    }

    // 2) Flash attention -> g_attn [M, D]
    {
        dim3 grid(S_ / 64, H_, B_);
        attn_kernel<<<grid, 64>>>(qkv, attn);
    }

    // 3) Output projection + bias -> d_out
    {
        dim3 grid(D_ / 128, M / 128);
        sgemm_kernel<false><<<grid, 256>>>(attn, w_o, b_o, nullptr, out,
                                           M, D_, D_);
    }
    (void)in_sizes; (void)n_in; (void)out_size;
}

// round 2
// speedup vs baseline: 1.2419x; 1.2419x over previous
#include <cuda_runtime.h>

#define B_  2
#define S_  2048
#define D_  1024
#define H_  16
#define HD_ 64

// Scratch (no cudaMalloc allowed)
__device__ float g_qkv[(size_t)B_ * S_ * 3 * D_];   // [B*S, 3*D] after proj+RoPE
__device__ float g_attn[(size_t)B_ * S_ * D_];      // [B*S, D]

// ---------------------------------------------------------------------------
// SGEMM: C[M,N] = A[M,K] @ W[N,K]^T + bias[N], optional fused RoPE.
// 128x128 tile, BK=8, 256 threads, 8x8 microtile, double-buffered SMEM with
// register prefetch of the next global tile.
// ---------------------------------------------------------------------------
template <bool ROPE>
__global__ void __launch_bounds__(256)
sgemm_kernel(const float* __restrict__ A, const float* __restrict__ W,
             const float* __restrict__ bias, const float* __restrict__ rot,
             float* __restrict__ C, int M, int N, int K)
{
    __shared__ float As[2][8][132];
    __shared__ float Ws[2][8][132];

    const int tid  = threadIdx.x;
    const int tx   = tid & 15;
    const int ty   = tid >> 4;
    const int arow = tid >> 1;
    const int acol = (tid & 1) * 4;

    const float* Ap = A + (size_t)(blockIdx.y * 128 + arow) * K + acol;
    const float* Wp = W + (size_t)(blockIdx.x * 128 + arow) * K + acol;

    float c[8][8];
#pragma unroll
    for (int i = 0; i < 8; i++)
#pragma unroll
        for (int j = 0; j < 8; j++) c[i][j] = 0.0f;

    // Preload tile 0 into buffer 0
    {
        float4 av = *(const float4*)(Ap);
        float4 wv = *(const float4*)(Wp);
        As[0][acol + 0][arow] = av.x;
        As[0][acol + 1][arow] = av.y;
        As[0][acol + 2][arow] = av.z;
        As[0][acol + 3][arow] = av.w;
        Ws[0][acol + 0][arow] = wv.x;
        Ws[0][acol + 1][arow] = wv.y;
        Ws[0][acol + 2][arow] = wv.z;
        Ws[0][acol + 3][arow] = wv.w;
    }
    __syncthreads();

    const int NT = K / 8;
    for (int t = 0; t < NT; t++) {
        const int cur = t & 1;
        float4 an, wn;
        const bool more = (t + 1 < NT);
        if (more) {
            an = *(const float4*)(Ap + (t + 1) * 8);
            wn = *(const float4*)(Wp + (t + 1) * 8);
        }

#pragma unroll
        for (int kk = 0; kk < 8; kk++) {
            float a[8], b[8];
            *(float4*)&a[0] = *(const float4*)&As[cur][kk][ty * 8];
            *(float4*)&a[4] = *(const float4*)&As[cur][kk][ty * 8 + 4];
            *(float4*)&b[0] = *(const float4*)&Ws[cur][kk][tx * 8];
            *(float4*)&b[4] = *(const float4*)&Ws[cur][kk][tx * 8 + 4];
#pragma unroll
            for (int i = 0; i < 8; i++)
#pragma unroll
                for (int j = 0; j < 8; j++)
                    c[i][j] += a[i] * b[j];
        }

        if (more) {
            const int nxt = cur ^ 1;
            As[nxt][acol + 0][arow] = an.x;
            As[nxt][acol + 1][arow] = an.y;
            As[nxt][acol + 2][arow] = an.z;
            As[nxt][acol + 3][arow] = an.w;
            Ws[nxt][acol + 0][arow] = wn.x;
            Ws[nxt][acol + 1][arow] = wn.y;
            Ws[nxt][acol + 2][arow] = wn.z;
            Ws[nxt][acol + 3][arow] = wn.w;
            __syncthreads();
        }
    }

    // Epilogue: bias + optional RoPE on adjacent column pairs
    const int row0 = blockIdx.y * 128 + ty * 8;
    const int col0 = blockIdx.x * 128 + tx * 8;
#pragma unroll
    for (int i = 0; i < 8; i++) {
        const int row = row0 + i;
        const int s   = row & (S_ - 1);
#pragma unroll
        for (int j = 0; j < 8; j += 2) {
            const int n = col0 + j;
            float e = c[i][j]     + bias[n];
            float o = c[i][j + 1] + bias[n + 1];
            float o0 = e, o1 = o;
            if (ROPE && n < 2 * D_) {
                const int d2 = n & (HD_ - 1);
                const float cs = rot[s * HD_ + d2];
                const float sn = rot[s * HD_ + d2 + 1];
                o0 = e * cs - o * sn;
                o1 = e * sn + o * cs;
            }
            C[(size_t)row * N + n]     = o0;
            C[(size_t)row * N + n + 1] = o1;
        }
    }
}

// ---------------------------------------------------------------------------
// Flash attention as a pair of tiled register GEMMs.
// Block: 256 threads (16x16). 64 queries per block, key tiles of 64.
// Qt, Kt stored transposed ([d][row]); K uses per-row XOR swizzle (float4
// granularity) for conflict-free reads AND cheap transposed stores.
// P (softmax probs) reuses Kt's buffer. All SMEM = exactly 48KB static.
// ---------------------------------------------------------------------------
__global__ void __launch_bounds__(256)
attn_kernel(const float* __restrict__ qkv, float* __restrict__ out)
{
    __shared__ float Qt[64 * 64];   // Qt[d*64 + q], pre-scaled
    __shared__ float KP[64 * 64];   // phase A: K^T swizzled; phase B: P[q][k]
    __shared__ float Vs[64 * 64];   // Vs[key*64 + d]

    const int tid = threadIdx.x;
    const int tx  = tid & 15;       // 0..15
    const int ty  = tid >> 4;       // 0..15
    const int b   = blockIdx.z;
    const int h   = blockIdx.y;
    const int q0  = blockIdx.x * 64;

    // Loader mapping: d4 = tid&15 (float4 col), jr = tid>>4 (row), 4 iters
    const int d4 = tx;
    const int jr = ty;

    // ---- Load Q tile transposed (scaled by 1/sqrt(HD)=0.125) ----
    const float* qb = qkv + ((size_t)(b * S_) + q0) * 3 * D_ + h * HD_;
#pragma unroll
    for (int it = 0; it < 4; it++) {
        const int j = jr + 16 * it;
        const float4 qv = *(const float4*)(qb + (size_t)j * 3 * D_ + 4 * d4);
        const int r = 4 * d4;
        Qt[(r + 0) * 64 + j] = qv.x * 0.125f;
        Qt[(r + 1) * 64 + j] = qv.y * 0.125f;
        Qt[(r + 2) * 64 + j] = qv.z * 0.125f;
        Qt[(r + 3) * 64 + j] = qv.w * 0.125f;
    }

    float o[4][4];
#pragma unroll
    for (int i = 0; i < 4; i++)
#pragma unroll
        for (int j = 0; j < 4; j++) o[i][j] = 0.0f;
    float m[4], l[4];
#pragma unroll
    for (int i = 0; i < 4; i++) { m[i] = -1e30f; l[i] = 0.0f; }

    for (int kt = 0; kt < S_; kt += 64) {
        // ---- Load K (transposed + swizzled) and V (natural) ----
        const float* kb = qkv + ((size_t)(b * S_) + kt) * 3 * D_ + D_ + h * HD_;
        const float* vb = kb + D_;
#pragma unroll
        for (int it = 0; it < 4; it++) {
            const int j = jr + 16 * it;
            const float4 kv = *(const float4*)(kb + (size_t)j * 3 * D_ + 4 * d4);
            const int ju = j >> 2, js = j & 3;
            {
                const int r = 4 * d4 + 0;
                KP[r * 64 + 4 * (ju ^ (r & 15)) + js] = kv.x;
            }
            {
                const int r = 4 * d4 + 1;
                KP[r * 64 + 4 * (ju ^ (r & 15)) + js] = kv.y;
            }
            {
                const int r = 4 * d4 + 2;
                KP[r * 64 + 4 * (ju ^ (r & 15)) + js] = kv.z;
            }
            {
                const int r = 4 * d4 + 3;
                KP[r * 64 + 4 * (ju ^ (r & 15)) + js] = kv.w;
            }
            const float4 vv = *(const float4*)(vb + (size_t)j * 3 * D_ + 4 * d4);
            *(float4*)&Vs[j * 64 + 4 * d4] = vv;
        }
        __syncthreads();

        // ---- Scores: s[4][4] = Q_tile(4 rows) . K_tile(4 cols) ----
        float s[4][4];
#pragma unroll
        for (int i = 0; i < 4; i++)
#pragma unroll
            for (int j = 0; j < 4; j++) s[i][j] = 0.0f;

#pragma unroll 16
        for (int kk = 0; kk < 64; kk++) {
            float a[4], bb[4];
            *(float4*)&a[0]  = *(const float4*)&Qt[kk * 64 + 4 * ty];
            *(float4*)&bb[0] = *(const float4*)&KP[kk * 64 + 4 * (tx ^ (kk & 15))];
#pragma unroll
            for (int i = 0; i < 4; i++)
#pragma unroll
                for (int j = 0; j < 4; j++)
                    s[i][j] += a[i] * bb[j];
        }

        // ---- Online softmax (row state replicated across the 16 tx lanes) --
        float tmax[4];
#pragma unroll
        for (int i = 0; i < 4; i++) {
            tmax[i] = fmaxf(fmaxf(s[i][0], s[i][1]), fmaxf(s[i][2], s[i][3]));
        }
#pragma unroll
        for (int w = 1; w < 16; w <<= 1)
#pragma unroll
            for (int i = 0; i < 4; i++)
                tmax[i] = fmaxf(tmax[i], __shfl_xor_sync(0xffffffffu, tmax[i], w));

        float alpha[4], rsum[4];
#pragma unroll
        for (int i = 0; i < 4; i++) {
            const float mnew = fmaxf(m[i], tmax[i]);
            alpha[i] = __expf(m[i] - mnew);
            m[i] = mnew;
            float rs = 0.0f;
#pragma unroll
            for (int j = 0; j < 4; j++) {
                s[i][j] = __expf(s[i][j] - mnew);
                rs += s[i][j];
            }
            rsum[i] = rs;
        }
#pragma unroll
        for (int w = 1; w < 16; w <<= 1)
#pragma unroll
            for (int i = 0; i < 4; i++)
                rsum[i] += __shfl_xor_sync(0xffffffffu, rsum[i], w);
#pragma unroll
        for (int i = 0; i < 4; i++) {
            l[i] = l[i] * alpha[i] + rsum[i];
#pragma unroll
            for (int j = 0; j < 4; j++) o[i][j] *= alpha[i];
        }

        __syncthreads();   // all score reads of KP done before P overwrites it

        // ---- Write P[q][k] into KP buffer ----
#pragma unroll
        for (int i = 0; i < 4; i++)
#pragma unroll
            for (int j = 0; j < 4; j++)
                KP[(4 * ty + i) * 64 + 4 * tx + j] = s[i][j];
        __syncthreads();

        // ---- PV: o[4 rows][4 d-cols] += P . V ----
#pragma unroll
        for (int k4 = 0; k4 < 16; k4++) {
            float pa[4][4];
#pragma unroll
            for (int i = 0; i < 4; i++)
                *(float4*)&pa[i][0] = *(const float4*)&KP[(4 * ty + i) * 64 + 4 * k4];
#pragma unroll
            for (int cc = 0; cc < 4; cc++) {
                float vvv[4];
                *(float4*)&vvv[0] = *(const float4*)&Vs[(4 * k4 + cc) * 64 + 4 * tx];
#pragma unroll
                for (int i = 0; i < 4; i++)
#pragma unroll
                    for (int j = 0; j < 4; j++)
                        o[i][j] += pa[i][cc] * vvv[j];
            }
        }
        __syncthreads();   // before next tile load overwrites KP/Vs
    }

    // ---- Epilogue ----
#pragma unroll
    for (int i = 0; i < 4; i++) {
        const float inv = 1.0f / l[i];
        const int row = b * S_ + q0 + 4 * ty + i;
        float4 ov;
        ov.x = o[i][0] * inv;
        ov.y = o[i][1] * inv;
        ov.z = o[i][2] * inv;
        ov.w = o[i][3] * inv;
        *(float4*)&out[(size_t)row * D_ + h * HD_ + 4 * tx] = ov;
    }
}

// ---------------------------------------------------------------------------
extern "C" void kernel_launch(void* const* d_in, const int* in_sizes, int n_in,
                              void* d_out, int out_size)
{
    const float* x     = (const float*)d_in[0];
    const float* rot   = (const float*)d_in[1];
    const float* w_qkv = (const float*)d_in[2];
    const float* b_qkv = (const float*)d_in[3];
    const float* w_o   = (const float*)d_in[4];
    const float* b_o   = (const float*)d_in[5];
    float* out = (float*)d_out;

    float* qkv  = nullptr;
    float* attn = nullptr;
    cudaGetSymbolAddress((void**)&qkv,  g_qkv);
    cudaGetSymbolAddress((void**)&attn, g_attn);

    const int M = B_ * S_;   // 4096

    {   // 1) QKV projection + bias + RoPE
        dim3 grid((3 * D_) / 128, M / 128);
        sgemm_kernel<true><<<grid, 256>>>(x, w_qkv, b_qkv, rot, qkv,
                                          M, 3 * D_, D_);
    }
    {   // 2) Flash attention
        dim3 grid(S_ / 64, H_, B_);
        attn_kernel<<<grid, 256>>>(qkv, attn);
    }
    {   // 3) Output projection + bias
        dim3 grid(D_ / 128, M / 128);
        sgemm_kernel<false><<<grid, 256>>>(attn, w_o, b_o, nullptr, out,
                                           M, D_, D_);
    }
    (void)in_sizes; (void)n_in; (void)out_size;
}

// round 4
// speedup vs baseline: 1.6471x; 1.3263x over previous
#include <cuda_runtime.h>
#include <cuda_bf16.h>
#include <cstdint>

#define B_  2
#define S_  2048
#define D_  1024
#define H_  16
#define HD_ 64
#define M_  (B_ * S_)   // 4096

// ---------------- device scratch (no cudaMalloc allowed) ----------------
__device__ float g_qkv[(size_t)M_ * 3 * D_];
__device__ float g_attn[(size_t)M_ * D_];
__device__ __nv_bfloat16 g_xhi[(size_t)M_ * D_];
__device__ __nv_bfloat16 g_xlo[(size_t)M_ * D_];
__device__ __nv_bfloat16 g_whi[(size_t)3 * D_ * D_];
__device__ __nv_bfloat16 g_wlo[(size_t)3 * D_ * D_];
__device__ __nv_bfloat16 g_wohi[(size_t)D_ * D_];
__device__ __nv_bfloat16 g_wolo[(size_t)D_ * D_];
__device__ __nv_bfloat16 g_ahi[(size_t)M_ * D_];
__device__ __nv_bfloat16 g_alo[(size_t)M_ * D_];

// ---------------- PTX helpers (portable: sm_80+ features only) ----------
__device__ __forceinline__ uint32_t smem_u32(const void* p) {
    uint32_t a;
    asm("{ .reg .u64 t; cvta.to.shared.u64 t, %1; cvt.u32.u64 %0, t; }"
        : "=r"(a) : "l"(p));
    return a;
}

#define CPA16(saddr, gptr) \
    asm volatile("cp.async.cg.shared.global [%0], [%1], 16;" \
                 :: "r"(saddr), "l"(gptr) : "memory")
#define CPA_COMMIT() asm volatile("cp.async.commit_group;" ::: "memory")
#define CPA_WAIT0()  asm volatile("cp.async.wait_group 0;" ::: "memory")

#define LDSM_X4(r, addr) \
    asm volatile("ldmatrix.sync.aligned.m8n8.x4.shared.b16 {%0,%1,%2,%3}, [%4];" \
                 : "=r"((r)[0]), "=r"((r)[1]), "=r"((r)[2]), "=r"((r)[3]) \
                 : "r"(addr))
#define LDSM_X2(r, addr) \
    asm volatile("ldmatrix.sync.aligned.m8n8.x2.shared.b16 {%0,%1}, [%2];" \
                 : "=r"((r)[0]), "=r"((r)[1]) : "r"(addr))

#define MMA16816(c, a, b) \
    asm volatile("mma.sync.aligned.m16n8k16.row.col.f32.bf16.bf16.f32 " \
                 "{%0,%1,%2,%3}, {%4,%5,%6,%7}, {%8,%9}, {%0,%1,%2,%3};" \
                 : "+f"((c)[0]), "+f"((c)[1]), "+f"((c)[2]), "+f"((c)[3]) \
                 : "r"((a)[0]), "r"((a)[1]), "r"((a)[2]), "r"((a)[3]), \
                   "r"((b)[0]), "r"((b)[1]))

// ---------------------------------------------------------------------------
// split: fp32 -> (hi, lo) bf16 pair
// ---------------------------------------------------------------------------
__global__ void __launch_bounds__(256)
split_kernel(const float4* __restrict__ src, __nv_bfloat162* __restrict__ hi,
             __nv_bfloat162* __restrict__ lo, int n4)
{
    int i = blockIdx.x * 256 + threadIdx.x;
    if (i >= n4) return;
    float4 v = src[i];
    __nv_bfloat162 h01 = __floats2bfloat162_rn(v.x, v.y);
    __nv_bfloat162 h23 = __floats2bfloat162_rn(v.z, v.w);
    float r0 = v.x - __low2float(h01);
    float r1 = v.y - __high2float(h01);
    float r2 = v.z - __low2float(h23);
    float r3 = v.w - __high2float(h23);
    hi[2 * i]     = h01;
    hi[2 * i + 1] = h23;
    lo[2 * i]     = __floats2bfloat162_rn(r0, r1);
    lo[2 * i + 1] = __floats2bfloat162_rn(r2, r3);
}

// ---------------------------------------------------------------------------
// Tensor-core GEMM via mma.sync bf16 (3-term compensated):
// C[M,N] = (Ahi+Alo)[M,K] @ (Bhi+Blo)[N,K]^T + bias, optional RoPE.
// 128x128 CTA tile, 8 warps (2m x 4n), warp tile 64x32, BK=32,
// double-buffered cp.async pipeline. Row stride 40 bf16 (conflict-free).
// ---------------------------------------------------------------------------
#define BKC      32
#define ASTRIDE  40
#define APART    (128 * ASTRIDE * 2)   // 10240 B per matrix part per stage
#define STAGE    (4 * APART)           // Ahi, Alo, Bhi, Blo
#define GSMEM    (2 * STAGE)           // 81920 B

template <bool ROPE>
__global__ void __launch_bounds__(256)
gemm_mma(const __nv_bfloat16* __restrict__ Ahi, const __nv_bfloat16* __restrict__ Alo,
         const __nv_bfloat16* __restrict__ Bhi, const __nv_bfloat16* __restrict__ Blo,
         const float* __restrict__ bias, const float* __restrict__ rot,
         float* __restrict__ C, int M, int N, int K)
{
    extern __shared__ __align__(16) char smem[];
    const uint32_t sb = smem_u32(smem);

    const int tid  = threadIdx.x;
    const int wid  = tid >> 5;
    const int lane = tid & 31;
    const int g    = lane >> 2;
    const int tg   = lane & 3;
    const int m0   = (wid & 1) * 64;
    const int n0   = (wid >> 1) * 32;

    // loader mapping: each thread owns one half-row (16 bf16) of each part
    const int lrow = tid >> 1;          // 0..127
    const int cseg = (tid & 1) * 16;    // bf16 col 0 or 16
    const uint32_t so = (uint32_t)lrow * (ASTRIDE * 2) + cseg * 2;

    const size_t rA = (size_t)(blockIdx.y * 128 + lrow) * K + cseg;
    const size_t rB = (size_t)(blockIdx.x * 128 + lrow) * K + cseg;
    const __nv_bfloat16* pAhi = Ahi + rA;
    const __nv_bfloat16* pAlo = Alo + rA;
    const __nv_bfloat16* pBhi = Bhi + rB;
    const __nv_bfloat16* pBlo = Blo + rB;

    // ldmatrix lane offsets (bytes)
    const uint32_t laneA = (uint32_t)((lane & 15) * ASTRIDE + 8 * (lane >> 4)) * 2;
    const uint32_t laneB = (uint32_t)((lane & 7) * ASTRIDE + 8 * ((lane >> 3) & 1)) * 2;

    float c[4][4][4];
#pragma unroll
    for (int mi = 0; mi < 4; mi++)
#pragma unroll
        for (int ni = 0; ni < 4; ni++)
#pragma unroll
            for (int e = 0; e < 4; e++) c[mi][ni][e] = 0.0f;

    const int NT = K / BKC;

    auto issue = [&](int t) {
        const uint32_t sbase = sb + (t & 1) * STAGE;
        const size_t k0 = (size_t)t * BKC;
        CPA16(sbase + so,                  pAhi + k0);
        CPA16(sbase + so + 16,             pAhi + k0 + 8);
        CPA16(sbase + APART + so,          pAlo + k0);
        CPA16(sbase + APART + so + 16,     pAlo + k0 + 8);
        CPA16(sbase + 2 * APART + so,      pBhi + k0);
        CPA16(sbase + 2 * APART + so + 16, pBhi + k0 + 8);
        CPA16(sbase + 3 * APART + so,      pBlo + k0);
        CPA16(sbase + 3 * APART + so + 16, pBlo + k0 + 8);
        CPA_COMMIT();
    };

    issue(0);
    CPA_WAIT0();
    __syncthreads();

    for (int t = 0; t < NT; t++) {
        const uint32_t sbase = sb + (t & 1) * STAGE;
        if (t + 1 < NT) issue(t + 1);

#pragma unroll
        for (int ks = 0; ks < 2; ks++) {
            const uint32_t k0b = ks * 32;   // 16 bf16 * 2 bytes
            const uint32_t aHiB = sbase + (uint32_t)m0 * (ASTRIDE * 2) + k0b + laneA;
            const uint32_t bHiB = sbase + 2 * APART + (uint32_t)n0 * (ASTRIDE * 2) + k0b + laneB;

            uint32_t ah[4][4], bh[4][2];
#pragma unroll
            for (int mi = 0; mi < 4; mi++)
                LDSM_X4(ah[mi], aHiB + mi * 16 * (ASTRIDE * 2));
#pragma unroll
            for (int ni = 0; ni < 4; ni++)
                LDSM_X2(bh[ni], bHiB + ni * 8 * (ASTRIDE * 2));

#pragma unroll
            for (int mi = 0; mi < 4; mi++)
#pragma unroll
                for (int ni = 0; ni < 4; ni++)
                    MMA16816(c[mi][ni], ah[mi], bh[ni]);

            {   // A_hi * B_lo
                uint32_t bl[4][2];
#pragma unroll
                for (int ni = 0; ni < 4; ni++)
                    LDSM_X2(bl[ni], bHiB + APART + ni * 8 * (ASTRIDE * 2));
#pragma unroll
                for (int mi = 0; mi < 4; mi++)
#pragma unroll
                    for (int ni = 0; ni < 4; ni++)
                        MMA16816(c[mi][ni], ah[mi], bl[ni]);
            }
            {   // A_lo * B_hi
                uint32_t al[4][4];
#pragma unroll
                for (int mi = 0; mi < 4; mi++)
                    LDSM_X4(al[mi], aHiB + APART + mi * 16 * (ASTRIDE * 2));
#pragma unroll
                for (int mi = 0; mi < 4; mi++)
#pragma unroll
                    for (int ni = 0; ni < 4; ni++)
                        MMA16816(c[mi][ni], al[mi], bh[ni]);
            }
        }

        if (t + 1 < NT) {
            CPA_WAIT0();
            __syncthreads();
        }
    }

    // ---- epilogue: bias + optional RoPE on (even, odd) column pairs ----
    const int row_base = blockIdx.y * 128 + m0;
    const int col_base = blockIdx.x * 128 + n0;
#pragma unroll
    for (int mi = 0; mi < 4; mi++) {
#pragma unroll
        for (int ni = 0; ni < 4; ni++) {
            const int col = col_base + ni * 8 + 2 * tg;
            const float2 bv = *(const float2*)&bias[col];
#pragma unroll
            for (int half = 0; half < 2; half++) {
                const int row = row_base + mi * 16 + g + 8 * half;
                float e = c[mi][ni][2 * half]     + bv.x;
                float o = c[mi][ni][2 * half + 1] + bv.y;
                float o0 = e, o1 = o;
                if (ROPE && col < 2 * D_) {
                    const int s = row & (S_ - 1);
                    const float2 cs = *(const float2*)&rot[s * HD_ + (col & (HD_ - 1))];
                    o0 = e * cs.x - o * cs.y;
                    o1 = e * cs.y + o * cs.x;
                }
                float2 ov; ov.x = o0; ov.y = o1;
                *(float2*)&C[(size_t)row * N + col] = ov;
            }
        }
    }
}

// ---------------------------------------------------------------------------
// Flash attention (round-2 version, fp32 FFMA)
// ---------------------------------------------------------------------------
__global__ void __launch_bounds__(256)
attn_kernel(const float* __restrict__ qkv, float* __restrict__ out)
{
    __shared__ float Qt[64 * 64];
    __shared__ float KP[64 * 64];
    __shared__ float Vs[64 * 64];

    const int tid = threadIdx.x;
    const int tx  = tid & 15;
    const int ty  = tid >> 4;
    const int b   = blockIdx.z;
    const int h   = blockIdx.y;
    const int q0  = blockIdx.x * 64;

    const int d4 = tx;
    const int jr = ty;

    const float* qb = qkv + ((size_t)(b * S_) + q0) * 3 * D_ + h * HD_;
#pragma unroll
    for (int it = 0; it < 4; it++) {
        const int j = jr + 16 * it;
        const float4 qv = *(const float4*)(qb + (size_t)j * 3 * D_ + 4 * d4);
        const int r = 4 * d4;
        Qt[(r + 0) * 64 + j] = qv.x * 0.125f;
        Qt[(r + 1) * 64 + j] = qv.y * 0.125f;
        Qt[(r + 2) * 64 + j] = qv.z * 0.125f;
        Qt[(r + 3) * 64 + j] = qv.w * 0.125f;
    }

    float o[4][4];
#pragma unroll
    for (int i = 0; i < 4; i++)
#pragma unroll
        for (int j = 0; j < 4; j++) o[i][j] = 0.0f;
    float m[4], l[4];
#pragma unroll
    for (int i = 0; i < 4; i++) { m[i] = -1e30f; l[i] = 0.0f; }

    for (int kt = 0; kt < S_; kt += 64) {
        const float* kb = qkv + ((size_t)(b * S_) + kt) * 3 * D_ + D_ + h * HD_;
        const float* vb = kb + D_;
#pragma unroll
        for (int it = 0; it < 4; it++) {
            const int j = jr + 16 * it;
            const float4 kv = *(const float4*)(kb + (size_t)j * 3 * D_ + 4 * d4);
            const int ju = j >> 2, js = j & 3;
            { const int r = 4 * d4 + 0; KP[r * 64 + 4 * (ju ^ (r & 15)) + js] = kv.x; }
            { const int r = 4 * d4 + 1; KP[r * 64 + 4 * (ju ^ (r & 15)) + js] = kv.y; }
            { const int r = 4 * d4 + 2; KP[r * 64 + 4 * (ju ^ (r & 15)) + js] = kv.z; }
            { const int r = 4 * d4 + 3; KP[r * 64 + 4 * (ju ^ (r & 15)) + js] = kv.w; }
            const float4 vv = *(const float4*)(vb + (size_t)j * 3 * D_ + 4 * d4);
            *(float4*)&Vs[j * 64 + 4 * d4] = vv;
        }
        __syncthreads();

        float s[4][4];
#pragma unroll
        for (int i = 0; i < 4; i++)
#pragma unroll
            for (int j = 0; j < 4; j++) s[i][j] = 0.0f;

#pragma unroll 16
        for (int kk = 0; kk < 64; kk++) {
            float a[4], bb[4];
            *(float4*)&a[0]  = *(const float4*)&Qt[kk * 64 + 4 * ty];
            *(float4*)&bb[0] = *(const float4*)&KP[kk * 64 + 4 * (tx ^ (kk & 15))];
#pragma unroll
            for (int i = 0; i < 4; i++)
#pragma unroll
                for (int j = 0; j < 4; j++)
                    s[i][j] += a[i] * bb[j];
        }

        float tmax[4];
#pragma unroll
        for (int i = 0; i < 4; i++)
            tmax[i] = fmaxf(fmaxf(s[i][0], s[i][1]), fmaxf(s[i][2], s[i][3]));
#pragma unroll
        for (int w = 1; w < 16; w <<= 1)
#pragma unroll
            for (int i = 0; i < 4; i++)
                tmax[i] = fmaxf(tmax[i], __shfl_xor_sync(0xffffffffu, tmax[i], w));

        float alpha[4], rsum[4];
#pragma unroll
        for (int i = 0; i < 4; i++) {
            const float mnew = fmaxf(m[i], tmax[i]);
            alpha[i] = __expf(m[i] - mnew);
            m[i] = mnew;
            float rs = 0.0f;
#pragma unroll
            for (int j = 0; j < 4; j++) {
                s[i][j] = __expf(s[i][j] - mnew);
                rs += s[i][j];
            }
            rsum[i] = rs;
        }
#pragma unroll
        for (int w = 1; w < 16; w <<= 1)
#pragma unroll
            for (int i = 0; i < 4; i++)
                rsum[i] += __shfl_xor_sync(0xffffffffu, rsum[i], w);
#pragma unroll
        for (int i = 0; i < 4; i++) {
            l[i] = l[i] * alpha[i] + rsum[i];
#pragma unroll
            for (int j = 0; j < 4; j++) o[i][j] *= alpha[i];
        }

        __syncthreads();

#pragma unroll
        for (int i = 0; i < 4; i++)
#pragma unroll
            for (int j = 0; j < 4; j++)
                KP[(4 * ty + i) * 64 + 4 * tx + j] = s[i][j];
        __syncthreads();

#pragma unroll
        for (int k4 = 0; k4 < 16; k4++) {
            float pa[4][4];
#pragma unroll
            for (int i = 0; i < 4; i++)
                *(float4*)&pa[i][0] = *(const float4*)&KP[(4 * ty + i) * 64 + 4 * k4];
#pragma unroll
            for (int cc = 0; cc < 4; cc++) {
                float vvv[4];
                *(float4*)&vvv[0] = *(const float4*)&Vs[(4 * k4 + cc) * 64 + 4 * tx];
#pragma unroll
                for (int i = 0; i < 4; i++)
#pragma unroll
                    for (int j = 0; j < 4; j++)
                        o[i][j] += pa[i][cc] * vvv[j];
            }
        }
        __syncthreads();
    }

#pragma unroll
    for (int i = 0; i < 4; i++) {
        const float inv = 1.0f / l[i];
        const int row = b * S_ + q0 + 4 * ty + i;
        float4 ov;
        ov.x = o[i][0] * inv;
        ov.y = o[i][1] * inv;
        ov.z = o[i][2] * inv;
        ov.w = o[i][3] * inv;
        *(float4*)&out[(size_t)row * D_ + h * HD_ + 4 * tx] = ov;
    }
}

// ---------------------------------------------------------------------------
extern "C" void kernel_launch(void* const* d_in, const int* in_sizes, int n_in,
                              void* d_out, int out_size)
{
    const float* x     = (const float*)d_in[0];
    const float* rot   = (const float*)d_in[1];
    const float* w_qkv = (const float*)d_in[2];
    const float* b_qkv = (const float*)d_in[3];
    const float* w_o   = (const float*)d_in[4];
    const float* b_o   = (const float*)d_in[5];
    float* out = (float*)d_out;

    float *qkv = nullptr, *attn = nullptr;
    __nv_bfloat16 *xhi, *xlo, *whi, *wlo, *wohi, *wolo, *ahi, *alo;
    cudaGetSymbolAddress((void**)&qkv,  g_qkv);
    cudaGetSymbolAddress((void**)&attn, g_attn);
    cudaGetSymbolAddress((void**)&xhi,  g_xhi);
    cudaGetSymbolAddress((void**)&xlo,  g_xlo);
    cudaGetSymbolAddress((void**)&whi,  g_whi);
    cudaGetSymbolAddress((void**)&wlo,  g_wlo);
    cudaGetSymbolAddress((void**)&wohi, g_wohi);
    cudaGetSymbolAddress((void**)&wolo, g_wolo);
    cudaGetSymbolAddress((void**)&ahi,  g_ahi);
    cudaGetSymbolAddress((void**)&alo,  g_alo);

    static bool attr_set = false;
    if (!attr_set) {
        cudaFuncSetAttribute(gemm_mma<true>,
                             cudaFuncAttributeMaxDynamicSharedMemorySize, GSMEM);
        cudaFuncSetAttribute(gemm_mma<false>,
                             cudaFuncAttributeMaxDynamicSharedMemorySize, GSMEM);
        attr_set = true;
    }

    // ---- split inputs/weights into bf16 hi/lo ----
    split_kernel<<<(M_ * D_ / 4) / 256, 256>>>(
        (const float4*)x, (__nv_bfloat162*)xhi, (__nv_bfloat162*)xlo, M_ * D_ / 4);
    split_kernel<<<(3 * D_ * D_ / 4) / 256, 256>>>(
        (const float4*)w_qkv, (__nv_bfloat162*)whi, (__nv_bfloat162*)wlo, 3 * D_ * D_ / 4);
    split_kernel<<<(D_ * D_ / 4) / 256, 256>>>(
        (const float4*)w_o, (__nv_bfloat162*)wohi, (__nv_bfloat162*)wolo, D_ * D_ / 4);

    // ---- 1) QKV projection + bias + RoPE (tensor core) ----
    {
        dim3 grid((3 * D_) / 128, M_ / 128);
        gemm_mma<true><<<grid, 256, GSMEM>>>(xhi, xlo, whi, wlo, b_qkv, rot,
                                             qkv, M_, 3 * D_, D_);
    }

    // ---- 2) Flash attention ----
    {
        dim3 grid(S_ / 64, H_, B_);
        attn_kernel<<<grid, 256>>>(qkv, attn);
    }

    // ---- split attention output, then 3) output projection ----
    split_kernel<<<(M_ * D_ / 4) / 256, 256>>>(
        (const float4*)attn, (__nv_bfloat162*)ahi, (__nv_bfloat162*)alo, M_ * D_ / 4);
    {
        dim3 grid(D_ / 128, M_ / 128);
        gemm_mma<false><<<grid, 256, GSMEM>>>(ahi, alo, wohi, wolo, b_o, nullptr,
                                              out, M_, D_, D_);
    }
    (void)in_sizes; (void)n_in; (void)out_size;
}

// round 5
// speedup vs baseline: 3.0540x; 1.8542x over previous
#include <cuda_runtime.h>
#include <cuda_bf16.h>
#include <cstdint>

#define B_  2
#define S_  2048
#define D_  1024
#define H_  16
#define HD_ 64
#define M_  (B_ * S_)   // 4096

// ---------------- device scratch (no cudaMalloc allowed) ----------------
__device__ __nv_bfloat16 g_xhi[(size_t)M_ * D_];
__device__ __nv_bfloat16 g_xlo[(size_t)M_ * D_];
__device__ __nv_bfloat16 g_whi[(size_t)3 * D_ * D_];
__device__ __nv_bfloat16 g_wlo[(size_t)3 * D_ * D_];
__device__ __nv_bfloat16 g_wohi[(size_t)D_ * D_];
__device__ __nv_bfloat16 g_wolo[(size_t)D_ * D_];
__device__ __nv_bfloat16 g_qh[(size_t)M_ * 3 * D_];   // qkv hi (q pre-scaled)
__device__ __nv_bfloat16 g_ql[(size_t)M_ * 3 * D_];   // qkv lo
__device__ __nv_bfloat16 g_ahi[(size_t)M_ * D_];      // attn out hi
__device__ __nv_bfloat16 g_alo[(size_t)M_ * D_];      // attn out lo

// ---------------- PTX helpers (sm_80+ portable) ----------------
__device__ __forceinline__ uint32_t smem_u32(const void* p) {
    uint32_t a;
    asm("{ .reg .u64 t; cvta.to.shared.u64 t, %1; cvt.u32.u64 %0, t; }"
        : "=r"(a) : "l"(p));
    return a;
}

#define CPA16(saddr, gptr) \
    asm volatile("cp.async.cg.shared.global [%0], [%1], 16;" \
                 :: "r"(saddr), "l"(gptr) : "memory")
#define CPA_COMMIT() asm volatile("cp.async.commit_group;" ::: "memory")
#define CPA_WAIT(n)  asm volatile("cp.async.wait_group %0;" :: "n"(n) : "memory")

#define LDSM_X4(r, addr) \
    asm volatile("ldmatrix.sync.aligned.m8n8.x4.shared.b16 {%0,%1,%2,%3}, [%4];" \
                 : "=r"((r)[0]), "=r"((r)[1]), "=r"((r)[2]), "=r"((r)[3]) \
                 : "r"(addr))
#define LDSM_X2(r, addr) \
    asm volatile("ldmatrix.sync.aligned.m8n8.x2.shared.b16 {%0,%1}, [%2];" \
                 : "=r"((r)[0]), "=r"((r)[1]) : "r"(addr))
#define LDSM_X2T(r, addr) \
    asm volatile("ldmatrix.sync.aligned.m8n8.x2.trans.shared.b16 {%0,%1}, [%2];" \
                 : "=r"((r)[0]), "=r"((r)[1]) : "r"(addr))

#define MMA16816(c, a, b) \
    asm volatile("mma.sync.aligned.m16n8k16.row.col.f32.bf16.bf16.f32 " \
                 "{%0,%1,%2,%3}, {%4,%5,%6,%7}, {%8,%9}, {%0,%1,%2,%3};" \
                 : "+f"((c)[0]), "+f"((c)[1]), "+f"((c)[2]), "+f"((c)[3]) \
                 : "r"((a)[0]), "r"((a)[1]), "r"((a)[2]), "r"((a)[3]), \
                   "r"((b)[0]), "r"((b)[1]))

__device__ __forceinline__ void split2(float x, float y, uint32_t& hi, uint32_t& lo) {
    __nv_bfloat162 h = __floats2bfloat162_rn(x, y);
    __nv_bfloat162 l = __floats2bfloat162_rn(x - __low2float(h), y - __high2float(h));
    hi = *(uint32_t*)&h;
    lo = *(uint32_t*)&l;
}

// ---------------------------------------------------------------------------
// split: fp32 -> (hi, lo) bf16 pair
// ---------------------------------------------------------------------------
__global__ void __launch_bounds__(256)
split_kernel(const float4* __restrict__ src, __nv_bfloat162* __restrict__ hi,
             __nv_bfloat162* __restrict__ lo, int n4)
{
    int i = blockIdx.x * 256 + threadIdx.x;
    if (i >= n4) return;
    float4 v = src[i];
    uint32_t h0, l0, h1, l1;
    split2(v.x, v.y, h0, l0);
    split2(v.z, v.w, h1, l1);
    hi[2 * i]     = *(__nv_bfloat162*)&h0;
    hi[2 * i + 1] = *(__nv_bfloat162*)&h1;
    lo[2 * i]     = *(__nv_bfloat162*)&l0;
    lo[2 * i + 1] = *(__nv_bfloat162*)&l1;
}

// ---------------------------------------------------------------------------
// Tensor-core GEMM (3-term bf16). SPLIT_OUT: write bf16 hi/lo (+RoPE, +0.125
// scale on q cols). Else: write fp32 + bias (output projection).
// ---------------------------------------------------------------------------
#define BKC      32
#define ASTRIDE  40
#define APART    (128 * ASTRIDE * 2)
#define STAGE    (4 * APART)
#define GSMEM    (2 * STAGE)

template <bool SPLIT_OUT>
__global__ void __launch_bounds__(256)
gemm_mma(const __nv_bfloat16* __restrict__ Ahi, const __nv_bfloat16* __restrict__ Alo,
         const __nv_bfloat16* __restrict__ Bhi, const __nv_bfloat16* __restrict__ Blo,
         const float* __restrict__ bias, const float* __restrict__ rot,
         float* __restrict__ C, __nv_bfloat16* __restrict__ Chi,
         __nv_bfloat16* __restrict__ Clo, int M, int N, int K)
{
    extern __shared__ __align__(16) char smem[];
    const uint32_t sb = smem_u32(smem);

    const int tid  = threadIdx.x;
    const int wid  = tid >> 5;
    const int lane = tid & 31;
    const int g    = lane >> 2;
    const int tg   = lane & 3;
    const int m0   = (wid & 1) * 64;
    const int n0   = (wid >> 1) * 32;

    const int lrow = tid >> 1;
    const int cseg = (tid & 1) * 16;
    const uint32_t so = (uint32_t)lrow * (ASTRIDE * 2) + cseg * 2;

    const size_t rA = (size_t)(blockIdx.y * 128 + lrow) * K + cseg;
    const size_t rB = (size_t)(blockIdx.x * 128 + lrow) * K + cseg;
    const __nv_bfloat16* pAhi = Ahi + rA;
    const __nv_bfloat16* pAlo = Alo + rA;
    const __nv_bfloat16* pBhi = Bhi + rB;
    const __nv_bfloat16* pBlo = Blo + rB;

    const uint32_t laneA = (uint32_t)((lane & 15) * ASTRIDE + 8 * (lane >> 4)) * 2;
    const uint32_t laneB = (uint32_t)((lane & 7) * ASTRIDE + 8 * ((lane >> 3) & 1)) * 2;

    float c[4][4][4];
#pragma unroll
    for (int mi = 0; mi < 4; mi++)
#pragma unroll
        for (int ni = 0; ni < 4; ni++)
#pragma unroll
            for (int e = 0; e < 4; e++) c[mi][ni][e] = 0.0f;

    const int NT = K / BKC;

    auto issue = [&](int t) {
        const uint32_t sbase = sb + (t & 1) * STAGE;
        const size_t k0 = (size_t)t * BKC;
        CPA16(sbase + so,                  pAhi + k0);
        CPA16(sbase + so + 16,             pAhi + k0 + 8);
        CPA16(sbase + APART + so,          pAlo + k0);
        CPA16(sbase + APART + so + 16,     pAlo + k0 + 8);
        CPA16(sbase + 2 * APART + so,      pBhi + k0);
        CPA16(sbase + 2 * APART + so + 16, pBhi + k0 + 8);
        CPA16(sbase + 3 * APART + so,      pBlo + k0);
        CPA16(sbase + 3 * APART + so + 16, pBlo + k0 + 8);
        CPA_COMMIT();
    };

    issue(0);
    CPA_WAIT(0);
    __syncthreads();

    for (int t = 0; t < NT; t++) {
        const uint32_t sbase = sb + (t & 1) * STAGE;
        if (t + 1 < NT) issue(t + 1);

#pragma unroll
        for (int ks = 0; ks < 2; ks++) {
            const uint32_t k0b = ks * 32;
            const uint32_t aHiB = sbase + (uint32_t)m0 * (ASTRIDE * 2) + k0b + laneA;
            const uint32_t bHiB = sbase + 2 * APART + (uint32_t)n0 * (ASTRIDE * 2) + k0b + laneB;

            uint32_t ah[4][4], bh[4][2];
#pragma unroll
            for (int mi = 0; mi < 4; mi++)
                LDSM_X4(ah[mi], aHiB + mi * 16 * (ASTRIDE * 2));
#pragma unroll
            for (int ni = 0; ni < 4; ni++)
                LDSM_X2(bh[ni], bHiB + ni * 8 * (ASTRIDE * 2));

#pragma unroll
            for (int mi = 0; mi < 4; mi++)
#pragma unroll
                for (int ni = 0; ni < 4; ni++)
                    MMA16816(c[mi][ni], ah[mi], bh[ni]);

            {
                uint32_t bl[4][2];
#pragma unroll
                for (int ni = 0; ni < 4; ni++)
                    LDSM_X2(bl[ni], bHiB + APART + ni * 8 * (ASTRIDE * 2));
#pragma unroll
                for (int mi = 0; mi < 4; mi++)
#pragma unroll
                    for (int ni = 0; ni < 4; ni++)
                        MMA16816(c[mi][ni], ah[mi], bl[ni]);
            }
            {
                uint32_t al[4][4];
#pragma unroll
                for (int mi = 0; mi < 4; mi++)
                    LDSM_X4(al[mi], aHiB + APART + mi * 16 * (ASTRIDE * 2));
#pragma unroll
                for (int mi = 0; mi < 4; mi++)
#pragma unroll
                    for (int ni = 0; ni < 4; ni++)
                        MMA16816(c[mi][ni], al[mi], bh[ni]);
            }
        }

        if (t + 1 < NT) {
            CPA_WAIT(0);
            __syncthreads();
        }
    }

    const int row_base = blockIdx.y * 128 + m0;
    const int col_base = blockIdx.x * 128 + n0;
#pragma unroll
    for (int mi = 0; mi < 4; mi++) {
#pragma unroll
        for (int ni = 0; ni < 4; ni++) {
            const int col = col_base + ni * 8 + 2 * tg;
            const float2 bv = *(const float2*)&bias[col];
#pragma unroll
            for (int half = 0; half < 2; half++) {
                const int row = row_base + mi * 16 + g + 8 * half;
                float e = c[mi][ni][2 * half]     + bv.x;
                float o = c[mi][ni][2 * half + 1] + bv.y;
                float o0 = e, o1 = o;
                if (SPLIT_OUT) {
                    if (col < 2 * D_) {   // RoPE on q and k
                        const int s = row & (S_ - 1);
                        const float2 cs = *(const float2*)&rot[s * HD_ + (col & (HD_ - 1))];
                        o0 = e * cs.x - o * cs.y;
                        o1 = e * cs.y + o * cs.x;
                    }
                    if (col < D_) {       // softmax scale on q (exact pow2)
                        o0 *= 0.125f;
                        o1 *= 0.125f;
                    }
                    uint32_t h2, l2;
                    split2(o0, o1, h2, l2);
                    *(uint32_t*)&Chi[(size_t)row * N + col] = h2;
                    *(uint32_t*)&Clo[(size_t)row * N + col] = l2;
                } else {
                    float2 ov; ov.x = o0; ov.y = o1;
                    *(float2*)&C[(size_t)row * N + col] = ov;
                }
            }
        }
    }
}

// ---------------------------------------------------------------------------
// Tensor-core flash attention (FA2-style), 3-term bf16 compensation.
// CTA: 128 q rows, 8 warps x 16 rows. K tiles of 128 keys, double-buffered.
// SMEM layout (bf16, stride 72/row): Qhi Qlo | buf0{Khi Klo Vhi Vlo} | buf1{...}
// ---------------------------------------------------------------------------
#define TSTR    72
#define TB      (128 * TSTR * 2)          // 18432 bytes per matrix
#define KVOFF   (2 * TB)
#define KVSZ    (4 * TB)
#define ATSMEM  (KVOFF + 2 * KVSZ)        // 184320

__global__ void __launch_bounds__(256)
attn_mma(const __nv_bfloat16* __restrict__ qh, const __nv_bfloat16* __restrict__ ql,
         __nv_bfloat16* __restrict__ ohi, __nv_bfloat16* __restrict__ olo)
{
    extern __shared__ __align__(16) char smem[];
    const uint32_t sb = smem_u32(smem);
    const int tid  = threadIdx.x;
    const int wid  = tid >> 5;
    const int lane = tid & 31;
    const int g    = lane >> 2;
    const int tg   = lane & 3;
    const int b    = blockIdx.z;
    const int h    = blockIdx.y;
    const int q0   = blockIdx.x * 128;

    // cooperative loader mapping
    const int lrow = tid >> 1;
    const int lseg = (tid & 1) * 4;

    // ---- issue Q copy ----
    {
        const size_t gq = ((size_t)(b * S_) + q0 + lrow) * (3 * D_) + h * HD_ + lseg * 8;
#pragma unroll
        for (int s = 0; s < 4; s++) {
            const uint32_t d = sb + (uint32_t)lrow * 144 + (lseg + s) * 16;
            CPA16(d,      qh + gq + s * 8);
            CPA16(d + TB, ql + gq + s * 8);
        }
    }

    auto issue_kv = [&](int t, int buf) {
        const size_t gk = ((size_t)(b * S_) + t * 128 + lrow) * (3 * D_) + D_ + h * HD_ + lseg * 8;
        const uint32_t base = sb + KVOFF + buf * KVSZ + (uint32_t)lrow * 144;
#pragma unroll
        for (int s = 0; s < 4; s++) {
            const uint32_t d = base + (lseg + s) * 16;
            CPA16(d,          qh + gk + s * 8);            // Khi
            CPA16(d + TB,     ql + gk + s * 8);            // Klo
            CPA16(d + 2 * TB, qh + gk + D_ + s * 8);       // Vhi
            CPA16(d + 3 * TB, ql + gk + D_ + s * 8);       // Vlo
        }
    };

    issue_kv(0, 0);
    CPA_COMMIT();     // group: Q + KV0

    // fragment lane offsets (bytes)
    const uint32_t laneA = (uint32_t)((lane & 15) * TSTR + 8 * (lane >> 4)) * 2;
    const uint32_t laneB = (uint32_t)((lane & 7) * TSTR + 8 * ((lane >> 3) & 1)) * 2;
    const uint32_t laneV = (uint32_t)((lane & 15) * TSTR) * 2;

    const uint32_t aQh = sb + (uint32_t)(16 * wid) * 144 + laneA;

    float o[8][4];
#pragma unroll
    for (int n = 0; n < 8; n++)
#pragma unroll
        for (int e = 0; e < 4; e++) o[n][e] = 0.0f;
    float mrow[2] = {-1e30f, -1e30f};
    float lsum[2] = {0.0f, 0.0f};

    uint32_t qfh[4][4], qfl[4][4];

    const int NKT = S_ / 128;   // 16
    for (int t = 0; t < NKT; t++) {
        if (t + 1 < NKT) {
            issue_kv(t + 1, (t + 1) & 1);
            CPA_COMMIT();
            CPA_WAIT(1);
        } else {
            CPA_WAIT(0);
        }
        __syncthreads();

        if (t == 0) {
#pragma unroll
            for (int ks = 0; ks < 4; ks++) {
                LDSM_X4(qfh[ks], aQh + ks * 32);
                LDSM_X4(qfl[ks], aQh + TB + ks * 32);
            }
        }

        const uint32_t kb = sb + KVOFF + (t & 1) * KVSZ;

        // ---- scores: c[16][4] = Q(16 rows) . K^T(128 cols), 3-term ----
        float c[16][4];
#pragma unroll
        for (int ni = 0; ni < 16; ni++)
#pragma unroll
            for (int e = 0; e < 4; e++) c[ni][e] = 0.0f;

#pragma unroll
        for (int ks = 0; ks < 4; ks++) {
#pragma unroll
            for (int ni = 0; ni < 16; ni++) {
                uint32_t bh[2], bl[2];
                const uint32_t a = kb + (uint32_t)(ni * 8) * 144 + ks * 32 + laneB;
                LDSM_X2(bh, a);
                LDSM_X2(bl, a + TB);
                MMA16816(c[ni], qfh[ks], bh);
                MMA16816(c[ni], qfh[ks], bl);
                MMA16816(c[ni], qfl[ks], bh);
            }
        }

        // ---- online softmax (rows g, g+8 of this warp's stripe) ----
        float tmax0 = -1e30f, tmax1 = -1e30f;
#pragma unroll
        for (int ni = 0; ni < 16; ni++) {
            tmax0 = fmaxf(tmax0, fmaxf(c[ni][0], c[ni][1]));
            tmax1 = fmaxf(tmax1, fmaxf(c[ni][2], c[ni][3]));
        }
        tmax0 = fmaxf(tmax0, __shfl_xor_sync(0xffffffffu, tmax0, 1));
        tmax0 = fmaxf(tmax0, __shfl_xor_sync(0xffffffffu, tmax0, 2));
        tmax1 = fmaxf(tmax1, __shfl_xor_sync(0xffffffffu, tmax1, 1));
        tmax1 = fmaxf(tmax1, __shfl_xor_sync(0xffffffffu, tmax1, 2));

        const float mn0 = fmaxf(mrow[0], tmax0);
        const float mn1 = fmaxf(mrow[1], tmax1);
        const float al0 = __expf(mrow[0] - mn0);
        const float al1 = __expf(mrow[1] - mn1);
        mrow[0] = mn0;
        mrow[1] = mn1;

        float s0 = 0.0f, s1 = 0.0f;
#pragma unroll
        for (int ni = 0; ni < 16; ni++) {
            c[ni][0] = __expf(c[ni][0] - mn0);
            c[ni][1] = __expf(c[ni][1] - mn0);
            c[ni][2] = __expf(c[ni][2] - mn1);
            c[ni][3] = __expf(c[ni][3] - mn1);
            s0 += c[ni][0] + c[ni][1];
            s1 += c[ni][2] + c[ni][3];
        }
        s0 += __shfl_xor_sync(0xffffffffu, s0, 1);
        s0 += __shfl_xor_sync(0xffffffffu, s0, 2);
        s1 += __shfl_xor_sync(0xffffffffu, s1, 1);
        s1 += __shfl_xor_sync(0xffffffffu, s1, 2);
        lsum[0] = lsum[0] * al0 + s0;
        lsum[1] = lsum[1] * al1 + s1;

#pragma unroll
        for (int n = 0; n < 8; n++) {
            o[n][0] *= al0; o[n][1] *= al0;
            o[n][2] *= al1; o[n][3] *= al1;
        }

        // ---- PV: o += P(16x128) . V(128x64), 3-term ----
        const uint32_t vb = kb + 2 * TB;
#pragma unroll
        for (int kj = 0; kj < 8; kj++) {
            uint32_t aph[4], apl[4];
            split2(c[2 * kj][0],     c[2 * kj][1],     aph[0], apl[0]);
            split2(c[2 * kj][2],     c[2 * kj][3],     aph[1], apl[1]);
            split2(c[2 * kj + 1][0], c[2 * kj + 1][1], aph[2], apl[2]);
            split2(c[2 * kj + 1][2], c[2 * kj + 1][3], aph[3], apl[3]);
#pragma unroll
            for (int n = 0; n < 8; n++) {
                uint32_t vh[2], vl[2];
                const uint32_t av = vb + (uint32_t)(16 * kj) * 144 + n * 16 + laneV;
                LDSM_X2T(vh, av);
                LDSM_X2T(vl, av + TB);
                MMA16816(o[n], aph, vh);
                MMA16816(o[n], aph, vl);
                MMA16816(o[n], apl, vh);
            }
        }
        __syncthreads();   // buffer reuse safety before next issue
    }

    // ---- epilogue: normalize, split to bf16 hi/lo ----
    const float inv0 = 1.0f / lsum[0];
    const float inv1 = 1.0f / lsum[1];
    const int r0 = b * S_ + q0 + 16 * wid + g;
    const int cb = h * HD_ + 2 * tg;
#pragma unroll
    for (int n = 0; n < 8; n++) {
        const int col = cb + 8 * n;
        uint32_t h2, l2;
        split2(o[n][0] * inv0, o[n][1] * inv0, h2, l2);
        *(uint32_t*)&ohi[(size_t)r0 * D_ + col] = h2;
        *(uint32_t*)&olo[(size_t)r0 * D_ + col] = l2;
        split2(o[n][2] * inv1, o[n][3] * inv1, h2, l2);
        *(uint32_t*)&ohi[(size_t)(r0 + 8) * D_ + col] = h2;
        *(uint32_t*)&olo[(size_t)(r0 + 8) * D_ + col] = l2;
    }
}

// ---------------------------------------------------------------------------
extern "C" void kernel_launch(void* const* d_in, const int* in_sizes, int n_in,
                              void* d_out, int out_size)
{
    const float* x     = (const float*)d_in[0];
    const float* rot   = (const float*)d_in[1];
    const float* w_qkv = (const float*)d_in[2];
    const float* b_qkv = (const float*)d_in[3];
    const float* w_o   = (const float*)d_in[4];
    const float* b_o   = (const float*)d_in[5];
    float* out = (float*)d_out;

    __nv_bfloat16 *xhi, *xlo, *whi, *wlo, *wohi, *wolo, *qh, *ql, *ahi, *alo;
    cudaGetSymbolAddress((void**)&xhi,  g_xhi);
    cudaGetSymbolAddress((void**)&xlo,  g_xlo);
    cudaGetSymbolAddress((void**)&whi,  g_whi);
    cudaGetSymbolAddress((void**)&wlo,  g_wlo);
    cudaGetSymbolAddress((void**)&wohi, g_wohi);
    cudaGetSymbolAddress((void**)&wolo, g_wolo);
    cudaGetSymbolAddress((void**)&qh,   g_qh);
    cudaGetSymbolAddress((void**)&ql,   g_ql);
    cudaGetSymbolAddress((void**)&ahi,  g_ahi);
    cudaGetSymbolAddress((void**)&alo,  g_alo);

    static bool attr_set = false;
    if (!attr_set) {
        cudaFuncSetAttribute(gemm_mma<true>,
                             cudaFuncAttributeMaxDynamicSharedMemorySize, GSMEM);
        cudaFuncSetAttribute(gemm_mma<false>,
                             cudaFuncAttributeMaxDynamicSharedMemorySize, GSMEM);
        cudaFuncSetAttribute(attn_mma,
                             cudaFuncAttributeMaxDynamicSharedMemorySize, ATSMEM);
        attr_set = true;
    }

    // ---- splits ----
    split_kernel<<<(M_ * D_ / 4) / 256, 256>>>(
        (const float4*)x, (__nv_bfloat162*)xhi, (__nv_bfloat162*)xlo, M_ * D_ / 4);
    split_kernel<<<(3 * D_ * D_ / 4) / 256, 256>>>(
        (const float4*)w_qkv, (__nv_bfloat162*)whi, (__nv_bfloat162*)wlo, 3 * D_ * D_ / 4);
    split_kernel<<<(D_ * D_ / 4) / 256, 256>>>(
        (const float4*)w_o, (__nv_bfloat162*)wohi, (__nv_bfloat162*)wolo, D_ * D_ / 4);

    // ---- 1) QKV projection + bias + RoPE + q-scale -> bf16 hi/lo ----
    {
        dim3 grid((3 * D_) / 128, M_ / 128);
        gemm_mma<true><<<grid, 256, GSMEM>>>(xhi, xlo, whi, wlo, b_qkv, rot,
                                             nullptr, qh, ql, M_, 3 * D_, D_);
    }

    // ---- 2) Tensor-core flash attention -> bf16 hi/lo ----
    {
        dim3 grid(S_ / 128, H_, B_);
        attn_mma<<<grid, 256, ATSMEM>>>(qh, ql, ahi, alo);
    }

    // ---- 3) Output projection + bias -> fp32 out ----
    {
        dim3 grid(D_ / 128, M_ / 128);
        gemm_mma<false><<<grid, 256, GSMEM>>>(ahi, alo, wohi, wolo, b_o, nullptr,
                                              out, nullptr, nullptr, M_, D_, D_);
    }
    (void)in_sizes; (void)n_in; (void)out_size;
}

// round 6
// speedup vs baseline: 4.5897x; 1.5028x over previous
#include <cuda_runtime.h>
#include <cuda_fp16.h>
#include <cstdint>

#define B_  2
#define S_  2048
#define D_  1024
#define H_  16
#define HD_ 64
#define M_  (B_ * S_)   // 4096

// ---------------- device scratch (no cudaMalloc allowed) ----------------
__device__ __half g_xhi[(size_t)M_ * D_];
__device__ __half g_xlo[(size_t)M_ * D_];
__device__ __half g_wh[(size_t)3 * D_ * D_];       // w_qkv rounded
__device__ __half g_woh[(size_t)D_ * D_];          // w_o rounded
__device__ __half g_qh[(size_t)M_ * 3 * D_];       // qkv hi (q pre-scaled)
__device__ __half g_ql[(size_t)M_ * D_];           // q lo only
__device__ __half g_ahi[(size_t)M_ * D_];          // attn out hi
__device__ __half g_alo[(size_t)M_ * D_];          // attn out lo

// ---------------- PTX helpers (sm_80+ portable) ----------------
__device__ __forceinline__ uint32_t smem_u32(const void* p) {
    uint32_t a;
    asm("{ .reg .u64 t; cvta.to.shared.u64 t, %1; cvt.u32.u64 %0, t; }"
        : "=r"(a) : "l"(p));
    return a;
}

#define CPA16(saddr, gptr) \
    asm volatile("cp.async.cg.shared.global [%0], [%1], 16;" \
                 :: "r"(saddr), "l"(gptr) : "memory")
#define CPA_COMMIT() asm volatile("cp.async.commit_group;" ::: "memory")
#define CPA_WAIT(n)  asm volatile("cp.async.wait_group %0;" :: "n"(n) : "memory")

#define LDSM_X4(r, addr) \
    asm volatile("ldmatrix.sync.aligned.m8n8.x4.shared.b16 {%0,%1,%2,%3}, [%4];" \
                 : "=r"((r)[0]), "=r"((r)[1]), "=r"((r)[2]), "=r"((r)[3]) \
                 : "r"(addr))
#define LDSM_X4T(r, addr) \
    asm volatile("ldmatrix.sync.aligned.m8n8.x4.trans.shared.b16 {%0,%1,%2,%3}, [%4];" \
                 : "=r"((r)[0]), "=r"((r)[1]), "=r"((r)[2]), "=r"((r)[3]) \
                 : "r"(addr))

#define MMAH(c, a, b) \
    asm volatile("mma.sync.aligned.m16n8k16.row.col.f32.f16.f16.f32 " \
                 "{%0,%1,%2,%3}, {%4,%5,%6,%7}, {%8,%9}, {%0,%1,%2,%3};" \
                 : "+f"((c)[0]), "+f"((c)[1]), "+f"((c)[2]), "+f"((c)[3]) \
                 : "r"((a)[0]), "r"((a)[1]), "r"((a)[2]), "r"((a)[3]), \
                   "r"((b)[0]), "r"((b)[1]))

__device__ __forceinline__ void split2h(float x, float y, uint32_t& hi, uint32_t& lo) {
    __half2 h = __floats2half2_rn(x, y);
    float2 hf = __half22float2(h);
    __half2 l = __floats2half2_rn(x - hf.x, y - hf.y);
    hi = *(uint32_t*)&h;
    lo = *(uint32_t*)&l;
}

// ---------------------------------------------------------------------------
// split: fp32 -> (hi, lo) fp16 pair;  round: fp32 -> fp16
// ---------------------------------------------------------------------------
__global__ void __launch_bounds__(256)
split_kernel(const float4* __restrict__ src, __half2* __restrict__ hi,
             __half2* __restrict__ lo, int n4)
{
    int i = blockIdx.x * 256 + threadIdx.x;
    if (i >= n4) return;
    float4 v = src[i];
    uint32_t h0, l0, h1, l1;
    split2h(v.x, v.y, h0, l0);
    split2h(v.z, v.w, h1, l1);
    hi[2 * i]     = *(__half2*)&h0;
    hi[2 * i + 1] = *(__half2*)&h1;
    lo[2 * i]     = *(__half2*)&l0;
    lo[2 * i + 1] = *(__half2*)&l1;
}

__global__ void __launch_bounds__(256)
round_kernel(const float4* __restrict__ src, __half2* __restrict__ dst, int n4)
{
    int i = blockIdx.x * 256 + threadIdx.x;
    if (i >= n4) return;
    float4 v = src[i];
    dst[2 * i]     = __floats2half2_rn(v.x, v.y);
    dst[2 * i + 1] = __floats2half2_rn(v.z, v.w);
}

// ---------------------------------------------------------------------------
// Tensor-core GEMM, 2-term fp16: C = (Ahi+Alo)[M,K] @ Bh[N,K]^T + bias.
// SPLIT_OUT: +RoPE (+0.125 q scale), writes fp16 (hi/lo for q, hi for k/v).
// 128x128 CTA tile, 8 warps (2m x 4n), BK=32, 3-stage cp.async pipeline.
// ---------------------------------------------------------------------------
#define BKC      32
#define ASTRIDE  40
#define STR2     (ASTRIDE * 2)
#define APART    (128 * STR2)           // 10240 B
#define STAGE    (3 * APART)            // Ahi, Alo, Bh
#define GSMEM    (3 * STAGE)            // 92160 B

template <bool SPLIT_OUT>
__global__ void __launch_bounds__(256)
gemm_mma(const __half* __restrict__ Ahi, const __half* __restrict__ Alo,
         const __half* __restrict__ Bh,
         const float* __restrict__ bias, const float* __restrict__ rot,
         float* __restrict__ C, __half* __restrict__ Chi,
         __half* __restrict__ Clo, int M, int N, int K)
{
    extern __shared__ __align__(16) char smem[];
    const uint32_t sb = smem_u32(smem);

    const int tid  = threadIdx.x;
    const int wid  = tid >> 5;
    const int lane = tid & 31;
    const int g    = lane >> 2;
    const int tg   = lane & 3;
    const int m0   = (wid & 1) * 64;
    const int n0   = (wid >> 1) * 32;

    const int lrow = tid >> 1;
    const int cseg = (tid & 1) * 16;
    const uint32_t so = (uint32_t)lrow * STR2 + cseg * 2;

    const size_t rA = (size_t)(blockIdx.y * 128 + lrow) * K + cseg;
    const size_t rB = (size_t)(blockIdx.x * 128 + lrow) * K + cseg;
    const __half* pAhi = Ahi + rA;
    const __half* pAlo = Alo + rA;
    const __half* pBh  = Bh + rB;

    // ldmatrix lane offsets (bytes)
    const uint32_t laneA  = (uint32_t)(lane & 15) * STR2 + (lane >> 4) * 16;
    const uint32_t laneB4 = (uint32_t)(lane & 7) * STR2 + ((lane >> 3) & 1) * 16
                          + (uint32_t)(lane >> 4) * 8 * STR2;

    float c[4][4][4];
#pragma unroll
    for (int mi = 0; mi < 4; mi++)
#pragma unroll
        for (int ni = 0; ni < 4; ni++)
#pragma unroll
            for (int e = 0; e < 4; e++) c[mi][ni][e] = 0.0f;

    const int NT = K / BKC;

    auto issue = [&](int t) {
        const uint32_t sbase = sb + (t % 3) * STAGE;
        const size_t k0 = (size_t)t * BKC;
        CPA16(sbase + so,                  pAhi + k0);
        CPA16(sbase + so + 16,             pAhi + k0 + 8);
        CPA16(sbase + APART + so,          pAlo + k0);
        CPA16(sbase + APART + so + 16,     pAlo + k0 + 8);
        CPA16(sbase + 2 * APART + so,      pBh + k0);
        CPA16(sbase + 2 * APART + so + 16, pBh + k0 + 8);
        CPA_COMMIT();
    };

    issue(0);
    issue(1);

    for (int t = 0; t < NT; t++) {
        CPA_WAIT(1);
        __syncthreads();
        if (t + 2 < NT) issue(t + 2);

        const uint32_t sbase = sb + (t % 3) * STAGE;
#pragma unroll
        for (int ks = 0; ks < 2; ks++) {
            const uint32_t k0b = ks * 32;
            const uint32_t aB = sbase + (uint32_t)m0 * STR2 + k0b + laneA;
            const uint32_t bB = sbase + 2 * APART + (uint32_t)n0 * STR2 + k0b + laneB4;

            uint32_t ah[4][4], al[4][4], bh[2][4];
#pragma unroll
            for (int mi = 0; mi < 4; mi++) {
                LDSM_X4(ah[mi], aB + mi * 16 * STR2);
                LDSM_X4(al[mi], aB + APART + mi * 16 * STR2);
            }
#pragma unroll
            for (int nj = 0; nj < 2; nj++)
                LDSM_X4(bh[nj], bB + nj * 16 * STR2);

#pragma unroll
            for (int mi = 0; mi < 4; mi++)
#pragma unroll
                for (int nj = 0; nj < 2; nj++) {
                    MMAH(c[mi][2 * nj],     ah[mi], (bh[nj] + 0));
                    MMAH(c[mi][2 * nj + 1], ah[mi], (bh[nj] + 2));
                    MMAH(c[mi][2 * nj],     al[mi], (bh[nj] + 0));
                    MMAH(c[mi][2 * nj + 1], al[mi], (bh[nj] + 2));
                }
        }
    }

    // ---- epilogue ----
    const int row_base = blockIdx.y * 128 + m0;
    const int col_base = blockIdx.x * 128 + n0;
#pragma unroll
    for (int mi = 0; mi < 4; mi++) {
#pragma unroll
        for (int ni = 0; ni < 4; ni++) {
            const int col = col_base + ni * 8 + 2 * tg;
            const float2 bv = *(const float2*)&bias[col];
#pragma unroll
            for (int half = 0; half < 2; half++) {
                const int row = row_base + mi * 16 + g + 8 * half;
                float e = c[mi][ni][2 * half]     + bv.x;
                float o = c[mi][ni][2 * half + 1] + bv.y;
                float o0 = e, o1 = o;
                if (SPLIT_OUT) {
                    if (col < 2 * D_) {   // RoPE on q and k
                        const int s = row & (S_ - 1);
                        const float2 cs = *(const float2*)&rot[s * HD_ + (col & (HD_ - 1))];
                        o0 = e * cs.x - o * cs.y;
                        o1 = e * cs.y + o * cs.x;
                    }
                    if (col < D_) {       // q: scale + split hi/lo
                        o0 *= 0.125f;
                        o1 *= 0.125f;
                        uint32_t h2, l2;
                        split2h(o0, o1, h2, l2);
                        *(uint32_t*)&Chi[(size_t)row * N + col] = h2;
                        *(uint32_t*)&Clo[(size_t)row * D_ + col] = l2;
                    } else {              // k, v: round to fp16 hi only
                        __half2 h = __floats2half2_rn(o0, o1);
                        *(__half2*)&Chi[(size_t)row * N + col] = h;
                    }
                } else {
                    float2 ov; ov.x = o0; ov.y = o1;
                    *(float2*)&C[(size_t)row * N + col] = ov;
                }
            }
        }
    }
}

// ---------------------------------------------------------------------------
// Tensor-core flash attention, 2-term fp16: Q split (hi/lo), K,V rounded.
// CTA: 128 q rows, 8 warps x 16 rows. K tiles of 128 keys, double-buffered.
// SMEM (fp16, stride 72): Qhi Qlo | buf0{Kh Vh} | buf1{Kh Vh}
// ---------------------------------------------------------------------------
#define TSTR    72
#define TSTR2   (TSTR * 2)
#define TB      (128 * TSTR2)             // 18432 bytes
#define KVOFF   (2 * TB)
#define KVSZ    (2 * TB)
#define ATSMEM  (KVOFF + 2 * KVSZ)        // 110592

__global__ void __launch_bounds__(256)
attn_mma(const __half* __restrict__ qh, const __half* __restrict__ ql,
         __half* __restrict__ ohi, __half* __restrict__ olo)
{
    extern __shared__ __align__(16) char smem[];
    const uint32_t sb = smem_u32(smem);
    const int tid  = threadIdx.x;
    const int wid  = tid >> 5;
    const int lane = tid & 31;
    const int g    = lane >> 2;
    const int tg   = lane & 3;
    const int b    = blockIdx.z;
    const int h    = blockIdx.y;
    const int q0   = blockIdx.x * 128;

    const int lrow = tid >> 1;
    const int lseg = (tid & 1) * 4;

    // ---- issue Q copy (hi from qh[3D layout], lo from ql[D layout]) ----
    {
        const size_t rowg = (size_t)(b * S_) + q0 + lrow;
        const size_t gqh = rowg * (3 * D_) + h * HD_ + lseg * 8;
        const size_t gql = rowg * D_ + h * HD_ + lseg * 8;
#pragma unroll
        for (int s = 0; s < 4; s++) {
            const uint32_t d = sb + (uint32_t)lrow * TSTR2 + (lseg + s) * 16;
            CPA16(d,      qh + gqh + s * 8);
            CPA16(d + TB, ql + gql + s * 8);
        }
    }

    auto issue_kv = [&](int t, int buf) {
        const size_t gk = ((size_t)(b * S_) + t * 128 + lrow) * (3 * D_) + D_ + h * HD_ + lseg * 8;
        const uint32_t base = sb + KVOFF + buf * KVSZ + (uint32_t)lrow * TSTR2;
#pragma unroll
        for (int s = 0; s < 4; s++) {
            const uint32_t d = base + (lseg + s) * 16;
            CPA16(d,      qh + gk + s * 8);        // K hi
            CPA16(d + TB, qh + gk + D_ + s * 8);   // V hi
        }
    };

    issue_kv(0, 0);
    CPA_COMMIT();     // group: Q + KV0

    // fragment lane offsets (bytes)
    const uint32_t laneA  = (uint32_t)(lane & 15) * TSTR2 + (lane >> 4) * 16;
    const uint32_t laneB4 = (uint32_t)(lane & 7) * TSTR2 + ((lane >> 3) & 1) * 16
                          + (uint32_t)(lane >> 4) * 8 * TSTR2;
    const uint32_t laneV4 = (uint32_t)(lane & 15) * TSTR2 + (lane >> 4) * 16;

    const uint32_t aQ = sb + (uint32_t)(16 * wid) * TSTR2 + laneA;

    float o[8][4];
#pragma unroll
    for (int n = 0; n < 8; n++)
#pragma unroll
        for (int e = 0; e < 4; e++) o[n][e] = 0.0f;
    float mrow[2] = {-1e30f, -1e30f};
    float lsum[2] = {0.0f, 0.0f};

    uint32_t qfh[4][4], qfl[4][4];

    const int NKT = S_ / 128;   // 16
    for (int t = 0; t < NKT; t++) {
        if (t + 1 < NKT) {
            issue_kv(t + 1, (t + 1) & 1);
            CPA_COMMIT();
            CPA_WAIT(1);
        } else {
            CPA_WAIT(0);
        }
        __syncthreads();

        if (t == 0) {
#pragma unroll
            for (int ks = 0; ks < 4; ks++) {
                LDSM_X4(qfh[ks], aQ + ks * 32);
                LDSM_X4(qfl[ks], aQ + TB + ks * 32);
            }
        }

        const uint32_t kb = sb + KVOFF + (t & 1) * KVSZ;

        // ---- scores: c[16][4] = Q(16 rows) . K^T(128 keys), 2-term ----
        float c[16][4];
#pragma unroll
        for (int ni = 0; ni < 16; ni++)
#pragma unroll
            for (int e = 0; e < 4; e++) c[ni][e] = 0.0f;

#pragma unroll
        for (int ks = 0; ks < 4; ks++) {
#pragma unroll
            for (int nj = 0; nj < 8; nj++) {
                uint32_t bh[4];
                LDSM_X4(bh, kb + (uint32_t)(nj * 16) * TSTR2 + ks * 32 + laneB4);
                MMAH(c[2 * nj],     qfh[ks], (bh + 0));
                MMAH(c[2 * nj + 1], qfh[ks], (bh + 2));
                MMAH(c[2 * nj],     qfl[ks], (bh + 0));
                MMAH(c[2 * nj + 1], qfl[ks], (bh + 2));
            }
        }

        // ---- online softmax ----
        float tmax0 = -1e30f, tmax1 = -1e30f;
#pragma unroll
        for (int ni = 0; ni < 16; ni++) {
            tmax0 = fmaxf(tmax0, fmaxf(c[ni][0], c[ni][1]));
            tmax1 = fmaxf(tmax1, fmaxf(c[ni][2], c[ni][3]));
        }
        tmax0 = fmaxf(tmax0, __shfl_xor_sync(0xffffffffu, tmax0, 1));
        tmax0 = fmaxf(tmax0, __shfl_xor_sync(0xffffffffu, tmax0, 2));
        tmax1 = fmaxf(tmax1, __shfl_xor_sync(0xffffffffu, tmax1, 1));
        tmax1 = fmaxf(tmax1, __shfl_xor_sync(0xffffffffu, tmax1, 2));

        const float mn0 = fmaxf(mrow[0], tmax0);
        const float mn1 = fmaxf(mrow[1], tmax1);
        const float al0 = __expf(mrow[0] - mn0);
        const float al1 = __expf(mrow[1] - mn1);
        mrow[0] = mn0;
        mrow[1] = mn1;

        float s0 = 0.0f, s1 = 0.0f;
#pragma unroll
        for (int ni = 0; ni < 16; ni++) {
            c[ni][0] = __expf(c[ni][0] - mn0);
            c[ni][1] = __expf(c[ni][1] - mn0);
            c[ni][2] = __expf(c[ni][2] - mn1);
            c[ni][3] = __expf(c[ni][3] - mn1);
            s0 += c[ni][0] + c[ni][1];
            s1 += c[ni][2] + c[ni][3];
        }
        s0 += __shfl_xor_sync(0xffffffffu, s0, 1);
        s0 += __shfl_xor_sync(0xffffffffu, s0, 2);
        s1 += __shfl_xor_sync(0xffffffffu, s1, 1);
        s1 += __shfl_xor_sync(0xffffffffu, s1, 2);
        lsum[0] = lsum[0] * al0 + s0;
        lsum[1] = lsum[1] * al1 + s1;

#pragma unroll
        for (int n = 0; n < 8; n++) {
            o[n][0] *= al0; o[n][1] *= al0;
            o[n][2] *= al1; o[n][3] *= al1;
        }

        // ---- PV: o += P(16x128) . V(128x64), P split 2-term ----
        const uint32_t vbb = kb + TB;
#pragma unroll
        for (int kj = 0; kj < 8; kj++) {
            uint32_t aph[4], apl[4];
            split2h(c[2 * kj][0],     c[2 * kj][1],     aph[0], apl[0]);
            split2h(c[2 * kj][2],     c[2 * kj][3],     aph[1], apl[1]);
            split2h(c[2 * kj + 1][0], c[2 * kj + 1][1], aph[2], apl[2]);
            split2h(c[2 * kj + 1][2], c[2 * kj + 1][3], aph[3], apl[3]);
#pragma unroll
            for (int np = 0; np < 4; np++) {
                uint32_t vh[4];
                LDSM_X4T(vh, vbb + (uint32_t)(16 * kj) * TSTR2 + np * 32 + laneV4);
                MMAH(o[2 * np],     aph, (vh + 0));
                MMAH(o[2 * np + 1], aph, (vh + 2));
                MMAH(o[2 * np],     apl, (vh + 0));
                MMAH(o[2 * np + 1], apl, (vh + 2));
            }
        }
        __syncthreads();   // buffer reuse safety
    }

    // ---- epilogue: normalize, split fp16 hi/lo ----
    const float inv0 = 1.0f / lsum[0];
    const float inv1 = 1.0f / lsum[1];
    const int r0 = b * S_ + q0 + 16 * wid + g;
    const int cb = h * HD_ + 2 * tg;
#pragma unroll
    for (int n = 0; n < 8; n++) {
        const int col = cb + 8 * n;
        uint32_t h2, l2;
        split2h(o[n][0] * inv0, o[n][1] * inv0, h2, l2);
        *(uint32_t*)&ohi[(size_t)r0 * D_ + col] = h2;
        *(uint32_t*)&olo[(size_t)r0 * D_ + col] = l2;
        split2h(o[n][2] * inv1, o[n][3] * inv1, h2, l2);
        *(uint32_t*)&ohi[(size_t)(r0 + 8) * D_ + col] = h2;
        *(uint32_t*)&olo[(size_t)(r0 + 8) * D_ + col] = l2;
    }
}

// ---------------------------------------------------------------------------
extern "C" void kernel_launch(void* const* d_in, const int* in_sizes, int n_in,
                              void* d_out, int out_size)
{
    const float* x     = (const float*)d_in[0];
    const float* rot   = (const float*)d_in[1];
    const float* w_qkv = (const float*)d_in[2];
    const float* b_qkv = (const float*)d_in[3];
    const float* w_o   = (const float*)d_in[4];
    const float* b_o   = (const float*)d_in[5];
    float* out = (float*)d_out;

    __half *xhi, *xlo, *wh, *woh, *qh, *ql, *ahi, *alo;
    cudaGetSymbolAddress((void**)&xhi, g_xhi);
    cudaGetSymbolAddress((void**)&xlo, g_xlo);
    cudaGetSymbolAddress((void**)&wh,  g_wh);
    cudaGetSymbolAddress((void**)&woh, g_woh);
    cudaGetSymbolAddress((void**)&qh,  g_qh);
    cudaGetSymbolAddress((void**)&ql,  g_ql);
    cudaGetSymbolAddress((void**)&ahi, g_ahi);
    cudaGetSymbolAddress((void**)&alo, g_alo);

    static bool attr_set = false;
    if (!attr_set) {
        cudaFuncSetAttribute(gemm_mma<true>,
                             cudaFuncAttributeMaxDynamicSharedMemorySize, GSMEM);
        cudaFuncSetAttribute(gemm_mma<false>,
                             cudaFuncAttributeMaxDynamicSharedMemorySize, GSMEM);
        cudaFuncSetAttribute(attn_mma,
                             cudaFuncAttributeMaxDynamicSharedMemorySize, ATSMEM);
        attr_set = true;
    }

    // ---- prep: split x, round weights ----
    split_kernel<<<(M_ * D_ / 4) / 256, 256>>>(
        (const float4*)x, (__half2*)xhi, (__half2*)xlo, M_ * D_ / 4);
    round_kernel<<<(3 * D_ * D_ / 4) / 256, 256>>>(
        (const float4*)w_qkv, (__half2*)wh, 3 * D_ * D_ / 4);
    round_kernel<<<(D_ * D_ / 4) / 256, 256>>>(
        (const float4*)w_o, (__half2*)woh, D_ * D_ / 4);

    // ---- 1) QKV projection + bias + RoPE + q-scale -> fp16 ----
    {
        dim3 grid((3 * D_) / 128, M_ / 128);
        gemm_mma<true><<<grid, 256, GSMEM>>>(xhi, xlo, wh, b_qkv, rot,
                                             nullptr, qh, ql, M_, 3 * D_, D_);
    }

    // ---- 2) Tensor-core flash attention -> fp16 hi/lo ----
    {
        dim3 grid(S_ / 128, H_, B_);
        attn_mma<<<grid, 256, ATSMEM>>>(qh, ql, ahi, alo);
    }

    // ---- 3) Output projection + bias -> fp32 out ----
    {
        dim3 grid(D_ / 128, M_ / 128);
        gemm_mma<false><<<grid, 256, GSMEM>>>(ahi, alo, woh, b_o, nullptr,
                                              out, nullptr, nullptr, M_, D_, D_);
    }
    (void)in_sizes; (void)n_in; (void)out_size;
}

// round 7
// speedup vs baseline: 6.7757x; 1.4763x over previous
#include <cuda_runtime.h>
#include <cuda_fp16.h>
#include <cstdint>

#define B_  2
#define S_  2048
#define D_  1024
#define H_  16
#define HD_ 64
#define M_  (B_ * S_)   // 4096

// ---------------- device scratch (no cudaMalloc allowed) ----------------
__device__ __half g_xh[(size_t)M_ * D_];           // x rounded
__device__ __half g_wh[(size_t)3 * D_ * D_];       // w_qkv rounded
__device__ __half g_woh[(size_t)D_ * D_];          // w_o rounded
__device__ __half g_qkv[(size_t)M_ * 3 * D_];      // qkv fp16 (q pre-scaled)
__device__ __half g_ah[(size_t)M_ * D_];           // attn out fp16

// ---------------- PTX helpers (sm_80+ portable) ----------------
__device__ __forceinline__ uint32_t smem_u32(const void* p) {
    uint32_t a;
    asm("{ .reg .u64 t; cvta.to.shared.u64 t, %1; cvt.u32.u64 %0, t; }"
        : "=r"(a) : "l"(p));
    return a;
}

#define CPA16(saddr, gptr) \
    asm volatile("cp.async.cg.shared.global [%0], [%1], 16;" \
                 :: "r"(saddr), "l"(gptr) : "memory")
#define CPA_COMMIT() asm volatile("cp.async.commit_group;" ::: "memory")
#define CPA_WAIT(n)  asm volatile("cp.async.wait_group %0;" :: "n"(n) : "memory")

#define LDSM_X4(r, addr) \
    asm volatile("ldmatrix.sync.aligned.m8n8.x4.shared.b16 {%0,%1,%2,%3}, [%4];" \
                 : "=r"((r)[0]), "=r"((r)[1]), "=r"((r)[2]), "=r"((r)[3]) \
                 : "r"(addr))
#define LDSM_X4T(r, addr) \
    asm volatile("ldmatrix.sync.aligned.m8n8.x4.trans.shared.b16 {%0,%1,%2,%3}, [%4];" \
                 : "=r"((r)[0]), "=r"((r)[1]), "=r"((r)[2]), "=r"((r)[3]) \
                 : "r"(addr))

#define MMAH(c, a, b) \
    asm volatile("mma.sync.aligned.m16n8k16.row.col.f32.f16.f16.f32 " \
                 "{%0,%1,%2,%3}, {%4,%5,%6,%7}, {%8,%9}, {%0,%1,%2,%3};" \
                 : "+f"((c)[0]), "+f"((c)[1]), "+f"((c)[2]), "+f"((c)[3]) \
                 : "r"((a)[0]), "r"((a)[1]), "r"((a)[2]), "r"((a)[3]), \
                   "r"((b)[0]), "r"((b)[1]))

// ---------------------------------------------------------------------------
// round: fp32 -> fp16
// ---------------------------------------------------------------------------
__global__ void __launch_bounds__(256)
round_kernel(const float4* __restrict__ src, __half2* __restrict__ dst, int n4)
{
    int i = blockIdx.x * 256 + threadIdx.x;
    if (i >= n4) return;
    float4 v = src[i];
    dst[2 * i]     = __floats2half2_rn(v.x, v.y);
    dst[2 * i + 1] = __floats2half2_rn(v.z, v.w);
}

// ---------------------------------------------------------------------------
// Tensor-core GEMM, 1-term fp16: C = Ah[M,K] @ Bh[N,K]^T + bias.
// SPLIT_OUT: +RoPE (+0.125 q scale), writes fp16. Else fp32 + bias.
// 128x128 CTA tile, 8 warps (2m x 4n), BK=32, 3-stage cp.async pipeline.
// ---------------------------------------------------------------------------
#define BKC      32
#define ASTRIDE  40
#define STR2     (ASTRIDE * 2)
#define APART    (128 * STR2)           // 10240 B
#define STAGE    (2 * APART)            // Ah, Bh
#define GSMEM    (3 * STAGE)            // 61440 B

template <bool SPLIT_OUT>
__global__ void __launch_bounds__(256)
gemm_mma(const __half* __restrict__ Ah, const __half* __restrict__ Bh,
         const float* __restrict__ bias, const float* __restrict__ rot,
         float* __restrict__ C, __half* __restrict__ Ch, int M, int N, int K)
{
    extern __shared__ __align__(16) char smem[];
    const uint32_t sb = smem_u32(smem);

    const int tid  = threadIdx.x;
    const int wid  = tid >> 5;
    const int lane = tid & 31;
    const int g    = lane >> 2;
    const int tg   = lane & 3;
    const int m0   = (wid & 1) * 64;
    const int n0   = (wid >> 1) * 32;

    const int lrow = tid >> 1;
    const int cseg = (tid & 1) * 16;
    const uint32_t so = (uint32_t)lrow * STR2 + cseg * 2;

    const size_t rA = (size_t)(blockIdx.y * 128 + lrow) * K + cseg;
    const size_t rB = (size_t)(blockIdx.x * 128 + lrow) * K + cseg;
    const __half* pAh = Ah + rA;
    const __half* pBh = Bh + rB;

    const uint32_t laneA  = (uint32_t)(lane & 15) * STR2 + (lane >> 4) * 16;
    const uint32_t laneB4 = (uint32_t)(lane & 7) * STR2 + ((lane >> 3) & 1) * 16
                          + (uint32_t)(lane >> 4) * 8 * STR2;

    float c[4][4][4];
#pragma unroll
    for (int mi = 0; mi < 4; mi++)
#pragma unroll
        for (int ni = 0; ni < 4; ni++)
#pragma unroll
            for (int e = 0; e < 4; e++) c[mi][ni][e] = 0.0f;

    const int NT = K / BKC;

    auto issue = [&](int t) {
        const uint32_t sbase = sb + (t % 3) * STAGE;
        const size_t k0 = (size_t)t * BKC;
        CPA16(sbase + so,              pAh + k0);
        CPA16(sbase + so + 16,         pAh + k0 + 8);
        CPA16(sbase + APART + so,      pBh + k0);
        CPA16(sbase + APART + so + 16, pBh + k0 + 8);
        CPA_COMMIT();
    };

    issue(0);
    issue(1);

    for (int t = 0; t < NT; t++) {
        CPA_WAIT(1);
        __syncthreads();
        if (t + 2 < NT) issue(t + 2);

        const uint32_t sbase = sb + (t % 3) * STAGE;
#pragma unroll
        for (int ks = 0; ks < 2; ks++) {
            const uint32_t k0b = ks * 32;
            const uint32_t aB = sbase + (uint32_t)m0 * STR2 + k0b + laneA;
            const uint32_t bB = sbase + APART + (uint32_t)n0 * STR2 + k0b + laneB4;

            uint32_t ah[4][4], bh[2][4];
#pragma unroll
            for (int mi = 0; mi < 4; mi++)
                LDSM_X4(ah[mi], aB + mi * 16 * STR2);
#pragma unroll
            for (int nj = 0; nj < 2; nj++)
                LDSM_X4(bh[nj], bB + nj * 16 * STR2);

#pragma unroll
            for (int mi = 0; mi < 4; mi++)
#pragma unroll
                for (int nj = 0; nj < 2; nj++) {
                    MMAH(c[mi][2 * nj],     ah[mi], (bh[nj] + 0));
                    MMAH(c[mi][2 * nj + 1], ah[mi], (bh[nj] + 2));
                }
        }
    }

    // ---- epilogue ----
    const int row_base = blockIdx.y * 128 + m0;
    const int col_base = blockIdx.x * 128 + n0;
#pragma unroll
    for (int mi = 0; mi < 4; mi++) {
#pragma unroll
        for (int ni = 0; ni < 4; ni++) {
            const int col = col_base + ni * 8 + 2 * tg;
            const float2 bv = *(const float2*)&bias[col];
#pragma unroll
            for (int half = 0; half < 2; half++) {
                const int row = row_base + mi * 16 + g + 8 * half;
                float e = c[mi][ni][2 * half]     + bv.x;
                float o = c[mi][ni][2 * half + 1] + bv.y;
                float o0 = e, o1 = o;
                if (SPLIT_OUT) {
                    if (col < 2 * D_) {   // RoPE on q and k
                        const int s = row & (S_ - 1);
                        const float2 cs = *(const float2*)&rot[s * HD_ + (col & (HD_ - 1))];
                        o0 = e * cs.x - o * cs.y;
                        o1 = e * cs.y + o * cs.x;
                    }
                    if (col < D_) {       // q: softmax scale (exact pow2)
                        o0 *= 0.125f;
                        o1 *= 0.125f;
                    }
                    __half2 hv = __floats2half2_rn(o0, o1);
                    *(__half2*)&Ch[(size_t)row * N + col] = hv;
                } else {
                    float2 ov; ov.x = o0; ov.y = o1;
                    *(float2*)&C[(size_t)row * N + col] = ov;
                }
            }
        }
    }
}

// ---------------------------------------------------------------------------
// Tensor-core flash attention, 1-term fp16.
// CTA: 128 q rows, 8 warps x 16 rows. K tiles of 128 keys, double-buffered.
// SMEM (fp16, stride 72): Q | buf0{Kh Vh} | buf1{Kh Vh}
// ---------------------------------------------------------------------------
#define TSTR    72
#define TSTR2   (TSTR * 2)
#define TB      (128 * TSTR2)             // 18432 bytes
#define KVOFF   TB
#define KVSZ    (2 * TB)
#define ATSMEM  (KVOFF + 2 * KVSZ)        // 92160

__global__ void __launch_bounds__(256)
attn_mma(const __half* __restrict__ qkv, __half* __restrict__ oh)
{
    extern __shared__ __align__(16) char smem[];
    const uint32_t sb = smem_u32(smem);
    const int tid  = threadIdx.x;
    const int wid  = tid >> 5;
    const int lane = tid & 31;
    const int g    = lane >> 2;
    const int tg   = lane & 3;
    const int b    = blockIdx.z;
    const int h    = blockIdx.y;
    const int q0   = blockIdx.x * 128;

    const int lrow = tid >> 1;
    const int lseg = (tid & 1) * 4;

    // ---- issue Q copy ----
    {
        const size_t gq = ((size_t)(b * S_) + q0 + lrow) * (3 * D_) + h * HD_ + lseg * 8;
#pragma unroll
        for (int s = 0; s < 4; s++)
            CPA16(sb + (uint32_t)lrow * TSTR2 + (lseg + s) * 16, qkv + gq + s * 8);
    }

    auto issue_kv = [&](int t, int buf) {
        const size_t gk = ((size_t)(b * S_) + t * 128 + lrow) * (3 * D_) + D_ + h * HD_ + lseg * 8;
        const uint32_t base = sb + KVOFF + buf * KVSZ + (uint32_t)lrow * TSTR2;
#pragma unroll
        for (int s = 0; s < 4; s++) {
            const uint32_t d = base + (lseg + s) * 16;
            CPA16(d,      qkv + gk + s * 8);        // K
            CPA16(d + TB, qkv + gk + D_ + s * 8);   // V
        }
    };

    issue_kv(0, 0);
    CPA_COMMIT();     // group: Q + KV0

    const uint32_t laneA  = (uint32_t)(lane & 15) * TSTR2 + (lane >> 4) * 16;
    const uint32_t laneB4 = (uint32_t)(lane & 7) * TSTR2 + ((lane >> 3) & 1) * 16
                          + (uint32_t)(lane >> 4) * 8 * TSTR2;
    const uint32_t laneV4 = (uint32_t)(lane & 15) * TSTR2 + (lane >> 4) * 16;

    const uint32_t aQ = sb + (uint32_t)(16 * wid) * TSTR2 + laneA;

    float o[8][4];
#pragma unroll
    for (int n = 0; n < 8; n++)
#pragma unroll
        for (int e = 0; e < 4; e++) o[n][e] = 0.0f;
    float mrow[2] = {-1e30f, -1e30f};
    float lsum[2] = {0.0f, 0.0f};

    uint32_t qf[4][4];

    const int NKT = S_ / 128;   // 16
    for (int t = 0; t < NKT; t++) {
        if (t + 1 < NKT) {
            issue_kv(t + 1, (t + 1) & 1);
            CPA_COMMIT();
            CPA_WAIT(1);
        } else {
            CPA_WAIT(0);
        }
        __syncthreads();

        if (t == 0) {
#pragma unroll
            for (int ks = 0; ks < 4; ks++)
                LDSM_X4(qf[ks], aQ + ks * 32);
        }

        const uint32_t kb = sb + KVOFF + (t & 1) * KVSZ;

        // ---- scores: c[16][4] = Q(16 rows) . K^T(128 keys) ----
        float c[16][4];
#pragma unroll
        for (int ni = 0; ni < 16; ni++)
#pragma unroll
            for (int e = 0; e < 4; e++) c[ni][e] = 0.0f;

#pragma unroll
        for (int ks = 0; ks < 4; ks++) {
#pragma unroll
            for (int nj = 0; nj < 8; nj++) {
                uint32_t bh[4];
                LDSM_X4(bh, kb + (uint32_t)(nj * 16) * TSTR2 + ks * 32 + laneB4);
                MMAH(c[2 * nj],     qf[ks], (bh + 0));
                MMAH(c[2 * nj + 1], qf[ks], (bh + 2));
            }
        }

        // ---- online softmax ----
        float tmax0 = -1e30f, tmax1 = -1e30f;
#pragma unroll
        for (int ni = 0; ni < 16; ni++) {
            tmax0 = fmaxf(tmax0, fmaxf(c[ni][0], c[ni][1]));
            tmax1 = fmaxf(tmax1, fmaxf(c[ni][2], c[ni][3]));
        }
        tmax0 = fmaxf(tmax0, __shfl_xor_sync(0xffffffffu, tmax0, 1));
        tmax0 = fmaxf(tmax0, __shfl_xor_sync(0xffffffffu, tmax0, 2));
        tmax1 = fmaxf(tmax1, __shfl_xor_sync(0xffffffffu, tmax1, 1));
        tmax1 = fmaxf(tmax1, __shfl_xor_sync(0xffffffffu, tmax1, 2));

        const float mn0 = fmaxf(mrow[0], tmax0);
        const float mn1 = fmaxf(mrow[1], tmax1);
        const float al0 = __expf(mrow[0] - mn0);
        const float al1 = __expf(mrow[1] - mn1);
        mrow[0] = mn0;
        mrow[1] = mn1;

        float s0 = 0.0f, s1 = 0.0f;
#pragma unroll
        for (int ni = 0; ni < 16; ni++) {
            c[ni][0] = __expf(c[ni][0] - mn0);
            c[ni][1] = __expf(c[ni][1] - mn0);
            c[ni][2] = __expf(c[ni][2] - mn1);
            c[ni][3] = __expf(c[ni][3] - mn1);
            s0 += c[ni][0] + c[ni][1];
            s1 += c[ni][2] + c[ni][3];
        }
        s0 += __shfl_xor_sync(0xffffffffu, s0, 1);
        s0 += __shfl_xor_sync(0xffffffffu, s0, 2);
        s1 += __shfl_xor_sync(0xffffffffu, s1, 1);
        s1 += __shfl_xor_sync(0xffffffffu, s1, 2);
        lsum[0] = lsum[0] * al0 + s0;
        lsum[1] = lsum[1] * al1 + s1;

#pragma unroll
        for (int n = 0; n < 8; n++) {
            o[n][0] *= al0; o[n][1] *= al0;
            o[n][2] *= al1; o[n][3] *= al1;
        }

        // ---- PV: o += P(16x128) . V(128x64), P rounded to fp16 ----
        const uint32_t vbb = kb + TB;
#pragma unroll
        for (int kj = 0; kj < 8; kj++) {
            uint32_t ap[4];
            {
                __half2 p0 = __floats2half2_rn(c[2 * kj][0],     c[2 * kj][1]);
                __half2 p1 = __floats2half2_rn(c[2 * kj][2],     c[2 * kj][3]);
                __half2 p2 = __floats2half2_rn(c[2 * kj + 1][0], c[2 * kj + 1][1]);
                __half2 p3 = __floats2half2_rn(c[2 * kj + 1][2], c[2 * kj + 1][3]);
                ap[0] = *(uint32_t*)&p0;
                ap[1] = *(uint32_t*)&p1;
                ap[2] = *(uint32_t*)&p2;
                ap[3] = *(uint32_t*)&p3;
            }
#pragma unroll
            for (int np = 0; np < 4; np++) {
                uint32_t vh[4];
                LDSM_X4T(vh, vbb + (uint32_t)(16 * kj) * TSTR2 + np * 32 + laneV4);
                MMAH(o[2 * np],     ap, (vh + 0));
                MMAH(o[2 * np + 1], ap, (vh + 2));
            }
        }
        __syncthreads();   // buffer reuse safety
    }

    // ---- epilogue: normalize, round to fp16 ----
    const float inv0 = 1.0f / lsum[0];
    const float inv1 = 1.0f / lsum[1];
    const int r0 = b * S_ + q0 + 16 * wid + g;
    const int cb = h * HD_ + 2 * tg;
#pragma unroll
    for (int n = 0; n < 8; n++) {
        const int col = cb + 8 * n;
        __half2 hv = __floats2half2_rn(o[n][0] * inv0, o[n][1] * inv0);
        *(__half2*)&oh[(size_t)r0 * D_ + col] = hv;
        hv = __floats2half2_rn(o[n][2] * inv1, o[n][3] * inv1);
        *(__half2*)&oh[(size_t)(r0 + 8) * D_ + col] = hv;
    }
}

// ---------------------------------------------------------------------------
extern "C" void kernel_launch(void* const* d_in, const int* in_sizes, int n_in,
                              void* d_out, int out_size)
{
    const float* x     = (const float*)d_in[0];
    const float* rot   = (const float*)d_in[1];
    const float* w_qkv = (const float*)d_in[2];
    const float* b_qkv = (const float*)d_in[3];
    const float* w_o   = (const float*)d_in[4];
    const float* b_o   = (const float*)d_in[5];
    float* out = (float*)d_out;

    __half *xh, *wh, *woh, *qkv, *ah;
    cudaGetSymbolAddress((void**)&xh,  g_xh);
    cudaGetSymbolAddress((void**)&wh,  g_wh);
    cudaGetSymbolAddress((void**)&woh, g_woh);
    cudaGetSymbolAddress((void**)&qkv, g_qkv);
    cudaGetSymbolAddress((void**)&ah,  g_ah);

    static bool attr_set = false;
    if (!attr_set) {
        cudaFuncSetAttribute(gemm_mma<true>,
                             cudaFuncAttributeMaxDynamicSharedMemorySize, GSMEM);
        cudaFuncSetAttribute(gemm_mma<false>,
                             cudaFuncAttributeMaxDynamicSharedMemorySize, GSMEM);
        cudaFuncSetAttribute(attn_mma,
                             cudaFuncAttributeMaxDynamicSharedMemorySize, ATSMEM);
        attr_set = true;
    }

    // ---- prep: round x and weights to fp16 ----
    round_kernel<<<(M_ * D_ / 4) / 256, 256>>>(
        (const float4*)x, (__half2*)xh, M_ * D_ / 4);
    round_kernel<<<(3 * D_ * D_ / 4) / 256, 256>>>(
        (const float4*)w_qkv, (__half2*)wh, 3 * D_ * D_ / 4);
    round_kernel<<<(D_ * D_ / 4) / 256, 256>>>(
        (const float4*)w_o, (__half2*)woh, D_ * D_ / 4);

    // ---- 1) QKV projection + bias + RoPE + q-scale -> fp16 ----
    {
        dim3 grid((3 * D_) / 128, M_ / 128);
        gemm_mma<true><<<grid, 256, GSMEM>>>(xh, wh, b_qkv, rot,
                                             nullptr, qkv, M_, 3 * D_, D_);
    }

    // ---- 2) Tensor-core flash attention -> fp16 ----
    {
        dim3 grid(S_ / 128, H_, B_);
        attn_mma<<<grid, 256, ATSMEM>>>(qkv, ah);
    }

    // ---- 3) Output projection + bias -> fp32 out ----
    {
        dim3 grid(D_ / 128, M_ / 128);
        gemm_mma<false><<<grid, 256, GSMEM>>>(ah, woh, b_o, nullptr,
                                              out, nullptr, M_, D_, D_);
    }
    (void)in_sizes; (void)n_in; (void)out_size;
}

// round 8
// speedup vs baseline: 7.4870x; 1.1050x over previous
#include <cuda_runtime.h>
#include <cuda_fp16.h>
#include <cstdint>

#define B_  2
#define S_  2048
#define D_  1024
#define H_  16
#define HD_ 64
#define M_  (B_ * S_)   // 4096

// ---------------- device scratch (no cudaMalloc allowed) ----------------
__device__ __half g_xh[(size_t)M_ * D_];           // x rounded
__device__ __half g_wh[(size_t)3 * D_ * D_];       // w_qkv rounded
__device__ __half g_woh[(size_t)D_ * D_];          // w_o rounded
__device__ __half g_qkv[(size_t)M_ * 3 * D_];      // qkv fp16 (q pre-scaled by 0.125*log2e)
__device__ __half g_ah[(size_t)M_ * D_];           // attn out fp16

// ---------------- PTX helpers (sm_80+ portable) ----------------
__device__ __forceinline__ uint32_t smem_u32(const void* p) {
    uint32_t a;
    asm("{ .reg .u64 t; cvta.to.shared.u64 t, %1; cvt.u32.u64 %0, t; }"
        : "=r"(a) : "l"(p));
    return a;
}

#define CPA16(saddr, gptr) \
    asm volatile("cp.async.cg.shared.global [%0], [%1], 16;" \
                 :: "r"(saddr), "l"(gptr) : "memory")
#define CPA_COMMIT() asm volatile("cp.async.commit_group;" ::: "memory")
#define CPA_WAIT(n)  asm volatile("cp.async.wait_group %0;" :: "n"(n) : "memory")

#define LDSM_X4(r, addr) \
    asm volatile("ldmatrix.sync.aligned.m8n8.x4.shared.b16 {%0,%1,%2,%3}, [%4];" \
                 : "=r"((r)[0]), "=r"((r)[1]), "=r"((r)[2]), "=r"((r)[3]) \
                 : "r"(addr))
#define LDSM_X4T(r, addr) \
    asm volatile("ldmatrix.sync.aligned.m8n8.x4.trans.shared.b16 {%0,%1,%2,%3}, [%4];" \
                 : "=r"((r)[0]), "=r"((r)[1]), "=r"((r)[2]), "=r"((r)[3]) \
                 : "r"(addr))

#define MMAH(c, a, b) \
    asm volatile("mma.sync.aligned.m16n8k16.row.col.f32.f16.f16.f32 " \
                 "{%0,%1,%2,%3}, {%4,%5,%6,%7}, {%8,%9}, {%0,%1,%2,%3};" \
                 : "+f"((c)[0]), "+f"((c)[1]), "+f"((c)[2]), "+f"((c)[3]) \
                 : "r"((a)[0]), "r"((a)[1]), "r"((a)[2]), "r"((a)[3]), \
                   "r"((b)[0]), "r"((b)[1]))

// ---------------------------------------------------------------------------
// round: fp32 -> fp16
// ---------------------------------------------------------------------------
__global__ void __launch_bounds__(256)
round_kernel(const float4* __restrict__ src, __half2* __restrict__ dst, int n4)
{
    int i = blockIdx.x * 256 + threadIdx.x;
    if (i >= n4) return;
    float4 v = src[i];
    dst[2 * i]     = __floats2half2_rn(v.x, v.y);
    dst[2 * i + 1] = __floats2half2_rn(v.z, v.w);
}

// ---------------------------------------------------------------------------
// Tensor-core GEMM, fp16: C = Ah[M,K] @ Bh[N,K]^T + bias.
// SPLIT_OUT: +RoPE (+0.125*log2e q scale), writes fp16. Else fp32 + bias.
// 128x128 CTA tile, 8 warps (2m x 4n), BK=32, 4-stage cp.async pipeline.
// ---------------------------------------------------------------------------
#define BKC      32
#define ASTRIDE  40
#define STR2     (ASTRIDE * 2)
#define APART    (128 * STR2)           // 10240 B
#define STAGE    (2 * APART)            // Ah, Bh
#define GSMEM    (4 * STAGE)            // 81920 B

#define QSCALE   0.18033688011112042f   // 0.125 * log2(e)

template <bool SPLIT_OUT>
__global__ void __launch_bounds__(256)
gemm_mma(const __half* __restrict__ Ah, const __half* __restrict__ Bh,
         const float* __restrict__ bias, const float* __restrict__ rot,
         float* __restrict__ C, __half* __restrict__ Ch, int M, int N, int K)
{
    extern __shared__ __align__(16) char smem[];
    const uint32_t sb = smem_u32(smem);

    const int tid  = threadIdx.x;
    const int wid  = tid >> 5;
    const int lane = tid & 31;
    const int g    = lane >> 2;
    const int tg   = lane & 3;
    const int m0   = (wid & 1) * 64;
    const int n0   = (wid >> 1) * 32;

    const int lrow = tid >> 1;
    const int cseg = (tid & 1) * 16;
    const uint32_t so = (uint32_t)lrow * STR2 + cseg * 2;

    const size_t rA = (size_t)(blockIdx.y * 128 + lrow) * K + cseg;
    const size_t rB = (size_t)(blockIdx.x * 128 + lrow) * K + cseg;
    const __half* pAh = Ah + rA;
    const __half* pBh = Bh + rB;

    const uint32_t laneA  = (uint32_t)(lane & 15) * STR2 + (lane >> 4) * 16;
    const uint32_t laneB4 = (uint32_t)(lane & 7) * STR2 + ((lane >> 3) & 1) * 16
                          + (uint32_t)(lane >> 4) * 8 * STR2;

    float c[4][4][4];
#pragma unroll
    for (int mi = 0; mi < 4; mi++)
#pragma unroll
        for (int ni = 0; ni < 4; ni++)
#pragma unroll
            for (int e = 0; e < 4; e++) c[mi][ni][e] = 0.0f;

    const int NT = K / BKC;

    auto issue = [&](int t) {
        const uint32_t sbase = sb + (t & 3) * STAGE;
        const size_t k0 = (size_t)t * BKC;
        CPA16(sbase + so,              pAh + k0);
        CPA16(sbase + so + 16,         pAh + k0 + 8);
        CPA16(sbase + APART + so,      pBh + k0);
        CPA16(sbase + APART + so + 16, pBh + k0 + 8);
        CPA_COMMIT();
    };

    issue(0);
    issue(1);
    issue(2);

    for (int t = 0; t < NT; t++) {
        if (t + 2 < NT)      CPA_WAIT(2);
        else if (t + 1 < NT) CPA_WAIT(1);
        else                 CPA_WAIT(0);
        __syncthreads();
        if (t + 3 < NT) issue(t + 3);

        const uint32_t sbase = sb + (t & 3) * STAGE;
#pragma unroll
        for (int ks = 0; ks < 2; ks++) {
            const uint32_t k0b = ks * 32;
            const uint32_t aB = sbase + (uint32_t)m0 * STR2 + k0b + laneA;
            const uint32_t bB = sbase + APART + (uint32_t)n0 * STR2 + k0b + laneB4;

            uint32_t ah[4][4], bh[2][4];
#pragma unroll
            for (int mi = 0; mi < 4; mi++)
                LDSM_X4(ah[mi], aB + mi * 16 * STR2);
#pragma unroll
            for (int nj = 0; nj < 2; nj++)
                LDSM_X4(bh[nj], bB + nj * 16 * STR2);

#pragma unroll
            for (int mi = 0; mi < 4; mi++)
#pragma unroll
                for (int nj = 0; nj < 2; nj++) {
                    MMAH(c[mi][2 * nj],     ah[mi], (bh[nj] + 0));
                    MMAH(c[mi][2 * nj + 1], ah[mi], (bh[nj] + 2));
                }
        }
    }

    // ---- epilogue ----
    const int row_base = blockIdx.y * 128 + m0;
    const int col_base = blockIdx.x * 128 + n0;
#pragma unroll
    for (int mi = 0; mi < 4; mi++) {
#pragma unroll
        for (int ni = 0; ni < 4; ni++) {
            const int col = col_base + ni * 8 + 2 * tg;
            const float2 bv = *(const float2*)&bias[col];
#pragma unroll
            for (int half = 0; half < 2; half++) {
                const int row = row_base + mi * 16 + g + 8 * half;
                float e = c[mi][ni][2 * half]     + bv.x;
                float o = c[mi][ni][2 * half + 1] + bv.y;
                float o0 = e, o1 = o;
                if (SPLIT_OUT) {
                    if (col < 2 * D_) {   // RoPE on q and k
                        const int s = row & (S_ - 1);
                        const float2 cs = *(const float2*)&rot[s * HD_ + (col & (HD_ - 1))];
                        o0 = e * cs.x - o * cs.y;
                        o1 = e * cs.y + o * cs.x;
                    }
                    if (col < D_) {       // q: softmax scale * log2(e)
                        o0 *= QSCALE;
                        o1 *= QSCALE;
                    }
                    __half2 hv = __floats2half2_rn(o0, o1);
                    *(__half2*)&Ch[(size_t)row * N + col] = hv;
                } else {
                    float2 ov; ov.x = o0; ov.y = o1;
                    *(float2*)&C[(size_t)row * N + col] = ov;
                }
            }
        }
    }
}

// ---------------------------------------------------------------------------
// Tensor-core flash attention, fp16, exp2-domain softmax.
// CTA: 128 q rows, 8 warps x 16 rows. K sub-tiles of 64 keys, 3-stage ring,
// one barrier per tile. 2 CTAs/SM (launch_bounds regs<=128).
// SMEM (fp16, stride 72): Q(128) | ring{K64,V64} x3
// ---------------------------------------------------------------------------
#define TSTR2   144
#define QB      (128 * TSTR2)             // 18432
#define KVST    (64 * TSTR2)              // 9216
#define STG     (2 * KVST)                // 18432 per stage
#define ATSMEM  (QB + 3 * STG)            // 73728

__global__ void __launch_bounds__(256, 2)
attn_mma(const __half* __restrict__ qkv, __half* __restrict__ oh)
{
    extern __shared__ __align__(16) char smem[];
    const uint32_t sb = smem_u32(smem);
    const int tid  = threadIdx.x;
    const int wid  = tid >> 5;
    const int lane = tid & 31;
    const int g    = lane >> 2;
    const int tg   = lane & 3;
    const int b    = blockIdx.z;
    const int h    = blockIdx.y;
    const int q0   = blockIdx.x * 128;

    // Q loader: 128 rows x 2 threads
    {
        const int lrow = tid >> 1;
        const int lseg = (tid & 1) * 4;
        const size_t gq = ((size_t)(b * S_) + q0 + lrow) * (3 * D_) + h * HD_ + lseg * 8;
#pragma unroll
        for (int s = 0; s < 4; s++)
            CPA16(sb + (uint32_t)lrow * TSTR2 + (lseg + s) * 16, qkv + gq + s * 8);
    }

    // KV loader: 64 rows x 4 threads
    const int krow = tid >> 2;
    const int kseg = (tid & 3) * 2;
    auto issue_kv = [&](int t) {
        const size_t gk = ((size_t)(b * S_) + t * 64 + krow) * (3 * D_) + D_ + h * HD_ + kseg * 8;
        const uint32_t base = sb + QB + (t % 3) * STG + (uint32_t)krow * TSTR2 + kseg * 16;
        CPA16(base,             qkv + gk);
        CPA16(base + 16,        qkv + gk + 8);
        CPA16(base + KVST,      qkv + gk + D_);
        CPA16(base + KVST + 16, qkv + gk + D_ + 8);
        CPA_COMMIT();
    };

    issue_kv(0);   // group 0 (also contains Q)
    issue_kv(1);   // group 1

    const uint32_t laneA  = (uint32_t)(lane & 15) * TSTR2 + (lane >> 4) * 16;
    const uint32_t laneB4 = (uint32_t)(lane & 7) * TSTR2 + ((lane >> 3) & 1) * 16
                          + (uint32_t)(lane >> 4) * 8 * TSTR2;
    const uint32_t laneV4 = (uint32_t)(lane & 15) * TSTR2 + (lane >> 4) * 16;

    const uint32_t aQ = sb + (uint32_t)(16 * wid) * TSTR2 + laneA;

    float o[8][4];
#pragma unroll
    for (int n = 0; n < 8; n++)
#pragma unroll
        for (int e = 0; e < 4; e++) o[n][e] = 0.0f;
    float mrow[2] = {-1e30f, -1e30f};
    float lsum[2] = {0.0f, 0.0f};

    uint32_t qf[4][4];

    const int NKT = S_ / 64;   // 32
    for (int t = 0; t < NKT; t++) {
        if (t + 1 < NKT) CPA_WAIT(1);
        else             CPA_WAIT(0);
        __syncthreads();
        if (t + 2 < NKT) issue_kv(t + 2);

        if (t == 0) {
#pragma unroll
            for (int ks = 0; ks < 4; ks++)
                LDSM_X4(qf[ks], aQ + ks * 32);
        }

        const uint32_t kb = sb + QB + (t % 3) * STG;

        // ---- scores: c[8][4] = Q(16 rows) . K^T(64 keys), log2 domain ----
        float c[8][4];
#pragma unroll
        for (int ni = 0; ni < 8; ni++)
#pragma unroll
            for (int e = 0; e < 4; e++) c[ni][e] = 0.0f;

#pragma unroll
        for (int ks = 0; ks < 4; ks++) {
#pragma unroll
            for (int nj = 0; nj < 4; nj++) {
                uint32_t bh[4];
                LDSM_X4(bh, kb + (uint32_t)(nj * 16) * TSTR2 + ks * 32 + laneB4);
                MMAH(c[2 * nj],     qf[ks], (bh + 0));
                MMAH(c[2 * nj + 1], qf[ks], (bh + 2));
            }
        }

        // ---- online softmax in exp2 domain ----
        float tmax0 = -1e30f, tmax1 = -1e30f;
#pragma unroll
        for (int ni = 0; ni < 8; ni++) {
            tmax0 = fmaxf(tmax0, fmaxf(c[ni][0], c[ni][1]));
            tmax1 = fmaxf(tmax1, fmaxf(c[ni][2], c[ni][3]));
        }
        tmax0 = fmaxf(tmax0, __shfl_xor_sync(0xffffffffu, tmax0, 1));
        tmax0 = fmaxf(tmax0, __shfl_xor_sync(0xffffffffu, tmax0, 2));
        tmax1 = fmaxf(tmax1, __shfl_xor_sync(0xffffffffu, tmax1, 1));
        tmax1 = fmaxf(tmax1, __shfl_xor_sync(0xffffffffu, tmax1, 2));

        const float mn0 = fmaxf(mrow[0], tmax0);
        const float mn1 = fmaxf(mrow[1], tmax1);
        const float al0 = exp2f(mrow[0] - mn0);
        const float al1 = exp2f(mrow[1] - mn1);
        mrow[0] = mn0;
        mrow[1] = mn1;

        float s0 = 0.0f, s1 = 0.0f;
#pragma unroll
        for (int ni = 0; ni < 8; ni++) {
            c[ni][0] = exp2f(c[ni][0] - mn0);
            c[ni][1] = exp2f(c[ni][1] - mn0);
            c[ni][2] = exp2f(c[ni][2] - mn1);
            c[ni][3] = exp2f(c[ni][3] - mn1);
            s0 += c[ni][0] + c[ni][1];
            s1 += c[ni][2] + c[ni][3];
        }
        s0 += __shfl_xor_sync(0xffffffffu, s0, 1);
        s0 += __shfl_xor_sync(0xffffffffu, s0, 2);
        s1 += __shfl_xor_sync(0xffffffffu, s1, 1);
        s1 += __shfl_xor_sync(0xffffffffu, s1, 2);
        lsum[0] = lsum[0] * al0 + s0;
        lsum[1] = lsum[1] * al1 + s1;

#pragma unroll
        for (int n = 0; n < 8; n++) {
            o[n][0] *= al0; o[n][1] *= al0;
            o[n][2] *= al1; o[n][3] *= al1;
        }

        // ---- PV: o += P(16x64) . V(64x64), P rounded to fp16 ----
        const uint32_t vbb = kb + KVST;
#pragma unroll
        for (int kj = 0; kj < 4; kj++) {
            uint32_t ap[4];
            {
                __half2 p0 = __floats2half2_rn(c[2 * kj][0],     c[2 * kj][1]);
                __half2 p1 = __floats2half2_rn(c[2 * kj][2],     c[2 * kj][3]);
                __half2 p2 = __floats2half2_rn(c[2 * kj + 1][0], c[2 * kj + 1][1]);
                __half2 p3 = __floats2half2_rn(c[2 * kj + 1][2], c[2 * kj + 1][3]);
                ap[0] = *(uint32_t*)&p0;
                ap[1] = *(uint32_t*)&p1;
                ap[2] = *(uint32_t*)&p2;
                ap[3] = *(uint32_t*)&p3;
            }
#pragma unroll
            for (int np = 0; np < 4; np++) {
                uint32_t vh[4];
                LDSM_X4T(vh, vbb + (uint32_t)(16 * kj) * TSTR2 + np * 32 + laneV4);
                MMAH(o[2 * np],     ap, (vh + 0));
                MMAH(o[2 * np + 1], ap, (vh + 2));
            }
        }
    }

    // ---- epilogue: normalize, round to fp16 ----
    const float inv0 = 1.0f / lsum[0];
    const float inv1 = 1.0f / lsum[1];
    const int r0 = b * S_ + q0 + 16 * wid + g;
    const int cb = h * HD_ + 2 * tg;
#pragma unroll
    for (int n = 0; n < 8; n++) {
        const int col = cb + 8 * n;
        __half2 hv = __floats2half2_rn(o[n][0] * inv0, o[n][1] * inv0);
        *(__half2*)&oh[(size_t)r0 * D_ + col] = hv;
        hv = __floats2half2_rn(o[n][2] * inv1, o[n][3] * inv1);
        *(__half2*)&oh[(size_t)(r0 + 8) * D_ + col] = hv;
    }
}

// ---------------------------------------------------------------------------
extern "C" void kernel_launch(void* const* d_in, const int* in_sizes, int n_in,
                              void* d_out, int out_size)
{
    const float* x     = (const float*)d_in[0];
    const float* rot   = (const float*)d_in[1];
    const float* w_qkv = (const float*)d_in[2];
    const float* b_qkv = (const float*)d_in[3];
    const float* w_o   = (const float*)d_in[4];
    const float* b_o   = (const float*)d_in[5];
    float* out = (float*)d_out;

    __half *xh, *wh, *woh, *qkv, *ah;
    cudaGetSymbolAddress((void**)&xh,  g_xh);
    cudaGetSymbolAddress((void**)&wh,  g_wh);
    cudaGetSymbolAddress((void**)&woh, g_woh);
    cudaGetSymbolAddress((void**)&qkv, g_qkv);
    cudaGetSymbolAddress((void**)&ah,  g_ah);

    static bool attr_set = false;
    if (!attr_set) {
        cudaFuncSetAttribute(gemm_mma<true>,
                             cudaFuncAttributeMaxDynamicSharedMemorySize, GSMEM);
        cudaFuncSetAttribute(gemm_mma<false>,
                             cudaFuncAttributeMaxDynamicSharedMemorySize, GSMEM);
        cudaFuncSetAttribute(attn_mma,
                             cudaFuncAttributeMaxDynamicSharedMemorySize, ATSMEM);
        attr_set = true;
    }

    // ---- prep: round x and weights to fp16 ----
    round_kernel<<<(M_ * D_ / 4) / 256, 256>>>(
        (const float4*)x, (__half2*)xh, M_ * D_ / 4);
    round_kernel<<<(3 * D_ * D_ / 4) / 256, 256>>>(
        (const float4*)w_qkv, (__half2*)wh, 3 * D_ * D_ / 4);
    round_kernel<<<(D_ * D_ / 4) / 256, 256>>>(
        (const float4*)w_o, (__half2*)woh, D_ * D_ / 4);

    // ---- 1) QKV projection + bias + RoPE + q-scale(log2e) -> fp16 ----
    {
        dim3 grid((3 * D_) / 128, M_ / 128);
        gemm_mma<true><<<grid, 256, GSMEM>>>(xh, wh, b_qkv, rot,
                                             nullptr, qkv, M_, 3 * D_, D_);
    }

    // ---- 2) Tensor-core flash attention -> fp16 ----
    {
        dim3 grid(S_ / 128, H_, B_);
        attn_mma<<<grid, 256, ATSMEM>>>(qkv, ah);
    }

    // ---- 3) Output projection + bias -> fp32 out ----
    {
        dim3 grid(D_ / 128, M_ / 128);
        gemm_mma<false><<<grid, 256, GSMEM>>>(ah, woh, b_o, nullptr,
                                              out, nullptr, M_, D_, D_);
    }
    (void)in_sizes; (void)n_in; (void)out_size;
}

// round 9
// speedup vs baseline: 7.6248x; 1.0184x over previous
#include <cuda_runtime.h>
#include <cuda_fp16.h>
#include <cstdint>

#define B_  2
#define S_  2048
#define D_  1024
#define H_  16
#define HD_ 64
#define M_  (B_ * S_)   // 4096

// ---------------- device scratch (no cudaMalloc allowed) ----------------
__device__ __half g_xh[(size_t)M_ * D_];           // x rounded
__device__ __half g_wh[(size_t)3 * D_ * D_];       // w_qkv rounded
__device__ __half g_woh[(size_t)D_ * D_];          // w_o rounded
__device__ __half g_qkv[(size_t)M_ * 3 * D_];      // qkv fp16 (q pre-scaled by 0.125*log2e)
__device__ __half g_ah[(size_t)M_ * D_];           // attn out fp16

// ---------------- PTX helpers (sm_80+ portable) ----------------
__device__ __forceinline__ uint32_t smem_u32(const void* p) {
    uint32_t a;
    asm("{ .reg .u64 t; cvta.to.shared.u64 t, %1; cvt.u32.u64 %0, t; }"
        : "=r"(a) : "l"(p));
    return a;
}

#define CPA16(saddr, gptr) \
    asm volatile("cp.async.cg.shared.global [%0], [%1], 16;" \
                 :: "r"(saddr), "l"(gptr) : "memory")
#define CPA_COMMIT() asm volatile("cp.async.commit_group;" ::: "memory")
#define CPA_WAIT(n)  asm volatile("cp.async.wait_group %0;" :: "n"(n) : "memory")

#define LDSM_X4(r, addr) \
    asm volatile("ldmatrix.sync.aligned.m8n8.x4.shared.b16 {%0,%1,%2,%3}, [%4];" \
                 : "=r"((r)[0]), "=r"((r)[1]), "=r"((r)[2]), "=r"((r)[3]) \
                 : "r"(addr))
#define LDSM_X4T(r, addr) \
    asm volatile("ldmatrix.sync.aligned.m8n8.x4.trans.shared.b16 {%0,%1,%2,%3}, [%4];" \
                 : "=r"((r)[0]), "=r"((r)[1]), "=r"((r)[2]), "=r"((r)[3]) \
                 : "r"(addr))

#define MMAH(c, a, b) \
    asm volatile("mma.sync.aligned.m16n8k16.row.col.f32.f16.f16.f32 " \
                 "{%0,%1,%2,%3}, {%4,%5,%6,%7}, {%8,%9}, {%0,%1,%2,%3};" \
                 : "+f"((c)[0]), "+f"((c)[1]), "+f"((c)[2]), "+f"((c)[3]) \
                 : "r"((a)[0]), "r"((a)[1]), "r"((a)[2]), "r"((a)[3]), \
                   "r"((b)[0]), "r"((b)[1]))

// ---------------------------------------------------------------------------
// fused prep: round x, w_qkv, w_o to fp16 in one grid-stride launch
// ---------------------------------------------------------------------------
#define N4_X   (M_ * D_ / 4)
#define N4_W   (3 * D_ * D_ / 4)
#define N4_WO  (D_ * D_ / 4)
#define N4_ALL (N4_X + N4_W + N4_WO)

__global__ void __launch_bounds__(256)
prep_kernel(const float4* __restrict__ x, const float4* __restrict__ w,
            const float4* __restrict__ wo, __half2* __restrict__ xh,
            __half2* __restrict__ wh, __half2* __restrict__ woh)
{
    int i = blockIdx.x * 256 + threadIdx.x;
    if (i >= N4_ALL) return;
    const float4* src;
    __half2* dst;
    int j;
    if (i < N4_X)            { src = x;  dst = xh;  j = i; }
    else if (i < N4_X + N4_W){ src = w;  dst = wh;  j = i - N4_X; }
    else                     { src = wo; dst = woh; j = i - N4_X - N4_W; }
    float4 v = src[j];
    dst[2 * j]     = __floats2half2_rn(v.x, v.y);
    dst[2 * j + 1] = __floats2half2_rn(v.z, v.w);
}

// ---------------------------------------------------------------------------
// Tensor-core GEMM, fp16: C = Ah[M,K] @ Bh[N,K]^T + bias.
// SPLIT_OUT: +RoPE (+0.125*log2e q scale), writes fp16. Else fp32 + bias.
// 128x128 CTA tile, 8 warps (2m x 4n), BK=32, 4-stage cp.async pipeline.
// ---------------------------------------------------------------------------
#define BKC      32
#define ASTRIDE  40
#define STR2     (ASTRIDE * 2)
#define APART    (128 * STR2)           // 10240 B
#define STAGE    (2 * APART)            // Ah, Bh
#define GSMEM    (4 * STAGE)            // 81920 B

#define QSCALE   0.18033688011112042f   // 0.125 * log2(e)

template <bool SPLIT_OUT>
__global__ void __launch_bounds__(256, 2)
gemm_mma(const __half* __restrict__ Ah, const __half* __restrict__ Bh,
         const float* __restrict__ bias, const float* __restrict__ rot,
         float* __restrict__ C, __half* __restrict__ Ch, int M, int N, int K)
{
    extern __shared__ __align__(16) char smem[];
    const uint32_t sb = smem_u32(smem);

    const int tid  = threadIdx.x;
    const int wid  = tid >> 5;
    const int lane = tid & 31;
    const int g    = lane >> 2;
    const int tg   = lane & 3;
    const int m0   = (wid & 1) * 64;
    const int n0   = (wid >> 1) * 32;

    const int lrow = tid >> 1;
    const int cseg = (tid & 1) * 16;
    const uint32_t so = (uint32_t)lrow * STR2 + cseg * 2;

    const size_t rA = (size_t)(blockIdx.y * 128 + lrow) * K + cseg;
    const size_t rB = (size_t)(blockIdx.x * 128 + lrow) * K + cseg;
    const __half* pAh = Ah + rA;
    const __half* pBh = Bh + rB;

    const uint32_t laneA  = (uint32_t)(lane & 15) * STR2 + (lane >> 4) * 16;
    const uint32_t laneB4 = (uint32_t)(lane & 7) * STR2 + ((lane >> 3) & 1) * 16
                          + (uint32_t)(lane >> 4) * 8 * STR2;

    float c[4][4][4];
#pragma unroll
    for (int mi = 0; mi < 4; mi++)
#pragma unroll
        for (int ni = 0; ni < 4; ni++)
#pragma unroll
            for (int e = 0; e < 4; e++) c[mi][ni][e] = 0.0f;

    const int NT = K / BKC;

    auto issue = [&](int t) {
        const uint32_t sbase = sb + (t & 3) * STAGE;
        const size_t k0 = (size_t)t * BKC;
        CPA16(sbase + so,              pAh + k0);
        CPA16(sbase + so + 16,         pAh + k0 + 8);
        CPA16(sbase + APART + so,      pBh + k0);
        CPA16(sbase + APART + so + 16, pBh + k0 + 8);
        CPA_COMMIT();
    };

    issue(0);
    issue(1);
    issue(2);

    for (int t = 0; t < NT; t++) {
        if (t + 2 < NT)      CPA_WAIT(2);
        else if (t + 1 < NT) CPA_WAIT(1);
        else                 CPA_WAIT(0);
        __syncthreads();
        if (t + 3 < NT) issue(t + 3);

        const uint32_t sbase = sb + (t & 3) * STAGE;
#pragma unroll
        for (int ks = 0; ks < 2; ks++) {
            const uint32_t k0b = ks * 32;
            const uint32_t aB = sbase + (uint32_t)m0 * STR2 + k0b + laneA;
            const uint32_t bB = sbase + APART + (uint32_t)n0 * STR2 + k0b + laneB4;

            uint32_t ah[4][4], bh[2][4];
#pragma unroll
            for (int mi = 0; mi < 4; mi++)
                LDSM_X4(ah[mi], aB + mi * 16 * STR2);
#pragma unroll
            for (int nj = 0; nj < 2; nj++)
                LDSM_X4(bh[nj], bB + nj * 16 * STR2);

#pragma unroll
            for (int mi = 0; mi < 4; mi++)
#pragma unroll
                for (int nj = 0; nj < 2; nj++) {
                    MMAH(c[mi][2 * nj],     ah[mi], (bh[nj] + 0));
                    MMAH(c[mi][2 * nj + 1], ah[mi], (bh[nj] + 2));
                }
        }
    }

    // ---- epilogue ----
    const int row_base = blockIdx.y * 128 + m0;
    const int col_base = blockIdx.x * 128 + n0;
#pragma unroll
    for (int mi = 0; mi < 4; mi++) {
#pragma unroll
        for (int ni = 0; ni < 4; ni++) {
            const int col = col_base + ni * 8 + 2 * tg;
            const float2 bv = *(const float2*)&bias[col];
#pragma unroll
            for (int half = 0; half < 2; half++) {
                const int row = row_base + mi * 16 + g + 8 * half;
                float e = c[mi][ni][2 * half]     + bv.x;
                float o = c[mi][ni][2 * half + 1] + bv.y;
                float o0 = e, o1 = o;
                if (SPLIT_OUT) {
                    if (col < 2 * D_) {   // RoPE on q and k
                        const int s = row & (S_ - 1);
                        const float2 cs = *(const float2*)&rot[s * HD_ + (col & (HD_ - 1))];
                        o0 = e * cs.x - o * cs.y;
                        o1 = e * cs.y + o * cs.x;
                    }
                    if (col < D_) {       // q: softmax scale * log2(e)
                        o0 *= QSCALE;
                        o1 *= QSCALE;
                    }
                    __half2 hv = __floats2half2_rn(o0, o1);
                    *(__half2*)&Ch[(size_t)row * N + col] = hv;
                } else {
                    float2 ov; ov.x = o0; ov.y = o1;
                    *(float2*)&C[(size_t)row * N + col] = ov;
                }
            }
        }
    }
}

// ---------------------------------------------------------------------------
// Tensor-core flash attention, fp16, exp2-domain softmax.
// CTA: 128 q rows, 8 warps x 16 rows. K sub-tiles of 64 keys, 4-stage ring
// (2 KV tiles of lookahead), one barrier per tile. 2 CTAs/SM.
// SMEM (fp16, stride 72): Q(128) | ring{K64,V64} x4
// ---------------------------------------------------------------------------
#define TSTR2   144
#define QB      (128 * TSTR2)             // 18432
#define KVST    (64 * TSTR2)              // 9216
#define STG     (2 * KVST)                // 18432 per stage
#define ATSMEM  (QB + 4 * STG)            // 92160

__global__ void __launch_bounds__(256, 2)
attn_mma(const __half* __restrict__ qkv, __half* __restrict__ oh)
{
    extern __shared__ __align__(16) char smem[];
    const uint32_t sb = smem_u32(smem);
    const int tid  = threadIdx.x;
    const int wid  = tid >> 5;
    const int lane = tid & 31;
    const int g    = lane >> 2;
    const int tg   = lane & 3;
    const int b    = blockIdx.z;
    const int h    = blockIdx.y;
    const int q0   = blockIdx.x * 128;

    // Q loader: 128 rows x 2 threads (part of commit group 0)
    {
        const int lrow = tid >> 1;
        const int lseg = (tid & 1) * 4;
        const size_t gq = ((size_t)(b * S_) + q0 + lrow) * (3 * D_) + h * HD_ + lseg * 8;
#pragma unroll
        for (int s = 0; s < 4; s++)
            CPA16(sb + (uint32_t)lrow * TSTR2 + (lseg + s) * 16, qkv + gq + s * 8);
    }

    // KV loader: 64 rows x 4 threads
    const int krow = tid >> 2;
    const int kseg = (tid & 3) * 2;
    auto issue_kv = [&](int t) {
        const size_t gk = ((size_t)(b * S_) + t * 64 + krow) * (3 * D_) + D_ + h * HD_ + kseg * 8;
        const uint32_t base = sb + QB + (t & 3) * STG + (uint32_t)krow * TSTR2 + kseg * 16;
        CPA16(base,             qkv + gk);
        CPA16(base + 16,        qkv + gk + 8);
        CPA16(base + KVST,      qkv + gk + D_);
        CPA16(base + KVST + 16, qkv + gk + D_ + 8);
        CPA_COMMIT();
    };

    issue_kv(0);   // group 0 (also contains Q)
    issue_kv(1);   // group 1
    issue_kv(2);   // group 2

    const uint32_t laneA  = (uint32_t)(lane & 15) * TSTR2 + (lane >> 4) * 16;
    const uint32_t laneB4 = (uint32_t)(lane & 7) * TSTR2 + ((lane >> 3) & 1) * 16
                          + (uint32_t)(lane >> 4) * 8 * TSTR2;
    const uint32_t laneV4 = (uint32_t)(lane & 15) * TSTR2 + (lane >> 4) * 16;

    const uint32_t aQ = sb + (uint32_t)(16 * wid) * TSTR2 + laneA;

    float o[8][4];
#pragma unroll
    for (int n = 0; n < 8; n++)
#pragma unroll
        for (int e = 0; e < 4; e++) o[n][e] = 0.0f;
    float mrow[2] = {-1e30f, -1e30f};
    float lsum[2] = {0.0f, 0.0f};

    uint32_t qf[4][4];

    const int NKT = S_ / 64;   // 32
    for (int t = 0; t < NKT; t++) {
        if (t + 2 < NKT)      CPA_WAIT(2);
        else if (t + 1 < NKT) CPA_WAIT(1);
        else                  CPA_WAIT(0);
        __syncthreads();
        if (t + 3 < NKT) issue_kv(t + 3);

        if (t == 0) {
#pragma unroll
            for (int ks = 0; ks < 4; ks++)
                LDSM_X4(qf[ks], aQ + ks * 32);
        }

        const uint32_t kb = sb + QB + (t & 3) * STG;

        // ---- scores: c[8][4] = Q(16 rows) . K^T(64 keys), log2 domain ----
        float c[8][4];
#pragma unroll
        for (int ni = 0; ni < 8; ni++)
#pragma unroll
            for (int e = 0; e < 4; e++) c[ni][e] = 0.0f;

#pragma unroll
        for (int ks = 0; ks < 4; ks++) {
#pragma unroll
            for (int nj = 0; nj < 4; nj++) {
                uint32_t bh[4];
                LDSM_X4(bh, kb + (uint32_t)(nj * 16) * TSTR2 + ks * 32 + laneB4);
                MMAH(c[2 * nj],     qf[ks], (bh + 0));
                MMAH(c[2 * nj + 1], qf[ks], (bh + 2));
            }
        }

        // ---- online softmax in exp2 domain ----
        float tmax0 = -1e30f, tmax1 = -1e30f;
#pragma unroll
        for (int ni = 0; ni < 8; ni++) {
            tmax0 = fmaxf(tmax0, fmaxf(c[ni][0], c[ni][1]));
            tmax1 = fmaxf(tmax1, fmaxf(c[ni][2], c[ni][3]));
        }
        tmax0 = fmaxf(tmax0, __shfl_xor_sync(0xffffffffu, tmax0, 1));
        tmax0 = fmaxf(tmax0, __shfl_xor_sync(0xffffffffu, tmax0, 2));
        tmax1 = fmaxf(tmax1, __shfl_xor_sync(0xffffffffu, tmax1, 1));
        tmax1 = fmaxf(tmax1, __shfl_xor_sync(0xffffffffu, tmax1, 2));

        const float mn0 = fmaxf(mrow[0], tmax0);
        const float mn1 = fmaxf(mrow[1], tmax1);
        const float al0 = exp2f(mrow[0] - mn0);
        const float al1 = exp2f(mrow[1] - mn1);
        mrow[0] = mn0;
        mrow[1] = mn1;

        float s0 = 0.0f, s1 = 0.0f;
#pragma unroll
        for (int ni = 0; ni < 8; ni++) {
            c[ni][0] = exp2f(c[ni][0] - mn0);
            c[ni][1] = exp2f(c[ni][1] - mn0);
            c[ni][2] = exp2f(c[ni][2] - mn1);
            c[ni][3] = exp2f(c[ni][3] - mn1);
            s0 += c[ni][0] + c[ni][1];
            s1 += c[ni][2] + c[ni][3];
        }
        s0 += __shfl_xor_sync(0xffffffffu, s0, 1);
        s0 += __shfl_xor_sync(0xffffffffu, s0, 2);
        s1 += __shfl_xor_sync(0xffffffffu, s1, 1);
        s1 += __shfl_xor_sync(0xffffffffu, s1, 2);
        lsum[0] = lsum[0] * al0 + s0;
        lsum[1] = lsum[1] * al1 + s1;

#pragma unroll
        for (int n = 0; n < 8; n++) {
            o[n][0] *= al0; o[n][1] *= al0;
            o[n][2] *= al1; o[n][3] *= al1;
        }

        // ---- PV: o += P(16x64) . V(64x64), P rounded to fp16 ----
        const uint32_t vbb = kb + KVST;
#pragma unroll
        for (int kj = 0; kj < 4; kj++) {
            uint32_t ap[4];
            {
                __half2 p0 = __floats2half2_rn(c[2 * kj][0],     c[2 * kj][1]);
                __half2 p1 = __floats2half2_rn(c[2 * kj][2],     c[2 * kj][3]);
                __half2 p2 = __floats2half2_rn(c[2 * kj + 1][0], c[2 * kj + 1][1]);
                __half2 p3 = __floats2half2_rn(c[2 * kj + 1][2], c[2 * kj + 1][3]);
                ap[0] = *(uint32_t*)&p0;
                ap[1] = *(uint32_t*)&p1;
                ap[2] = *(uint32_t*)&p2;
                ap[3] = *(uint32_t*)&p3;
            }
#pragma unroll
            for (int np = 0; np < 4; np++) {
                uint32_t vh[4];
                LDSM_X4T(vh, vbb + (uint32_t)(16 * kj) * TSTR2 + np * 32 + laneV4);
                MMAH(o[2 * np],     ap, (vh + 0));
                MMAH(o[2 * np + 1], ap, (vh + 2));
            }
        }
    }

    // ---- epilogue: normalize, round to fp16 ----
    const float inv0 = 1.0f / lsum[0];
    const float inv1 = 1.0f / lsum[1];
    const int r0 = b * S_ + q0 + 16 * wid + g;
    const int cb = h * HD_ + 2 * tg;
#pragma unroll
    for (int n = 0; n < 8; n++) {
        const int col = cb + 8 * n;
        __half2 hv = __floats2half2_rn(o[n][0] * inv0, o[n][1] * inv0);
        *(__half2*)&oh[(size_t)r0 * D_ + col] = hv;
        hv = __floats2half2_rn(o[n][2] * inv1, o[n][3] * inv1);
        *(__half2*)&oh[(size_t)(r0 + 8) * D_ + col] = hv;
    }
}

// ---------------------------------------------------------------------------
extern "C" void kernel_launch(void* const* d_in, const int* in_sizes, int n_in,
                              void* d_out, int out_size)
{
    const float* x     = (const float*)d_in[0];
    const float* rot   = (const float*)d_in[1];
    const float* w_qkv = (const float*)d_in[2];
    const float* b_qkv = (const float*)d_in[3];
    const float* w_o   = (const float*)d_in[4];
    const float* b_o   = (const float*)d_in[5];
    float* out = (float*)d_out;

    __half *xh, *wh, *woh, *qkv, *ah;
    cudaGetSymbolAddress((void**)&xh,  g_xh);
    cudaGetSymbolAddress((void**)&wh,  g_wh);
    cudaGetSymbolAddress((void**)&woh, g_woh);
    cudaGetSymbolAddress((void**)&qkv, g_qkv);
    cudaGetSymbolAddress((void**)&ah,  g_ah);

    static bool attr_set = false;
    if (!attr_set) {
        cudaFuncSetAttribute(gemm_mma<true>,
                             cudaFuncAttributeMaxDynamicSharedMemorySize, GSMEM);
        cudaFuncSetAttribute(gemm_mma<false>,
                             cudaFuncAttributeMaxDynamicSharedMemorySize, GSMEM);
        cudaFuncSetAttribute(attn_mma,
                             cudaFuncAttributeMaxDynamicSharedMemorySize, ATSMEM);
        attr_set = true;
    }

    // ---- prep: round x and weights to fp16 (single fused launch) ----
    prep_kernel<<<(N4_ALL + 255) / 256, 256>>>(
        (const float4*)x, (const float4*)w_qkv, (const float4*)w_o,
        (__half2*)xh, (__half2*)wh, (__half2*)woh);

    // ---- 1) QKV projection + bias + RoPE + q-scale(log2e) -> fp16 ----
    {
        dim3 grid((3 * D_) / 128, M_ / 128);
        gemm_mma<true><<<grid, 256, GSMEM>>>(xh, wh, b_qkv, rot,
                                             nullptr, qkv, M_, 3 * D_, D_);
    }

    // ---- 2) Tensor-core flash attention -> fp16 ----
    {
        dim3 grid(S_ / 128, H_, B_);
        attn_mma<<<grid, 256, ATSMEM>>>(qkv, ah);
    }

    // ---- 3) Output projection + bias -> fp32 out ----
    {
        dim3 grid(D_ / 128, M_ / 128);
        gemm_mma<false><<<grid, 256, GSMEM>>>(ah, woh, b_o, nullptr,
                                              out, nullptr, M_, D_, D_);
    }
    (void)in_sizes; (void)n_in; (void)out_size;
}